// round 11
// baseline (speedup 1.0000x reference)
#include <cuda_runtime.h>
#include <cuda_bf16.h>
#include <math.h>

#define TILE_M 128
#define THREADS 256
#define SAB 136                 // bf16 per smem row (272B) -> conflict-free LDSM
#define ROWB (SAB * 2)          // 272 bytes per row
#define TILE_B (128 * ROWB)     // 34816 bytes per 128x128 tile

#define MAX_N 100096
#define W1_OFF 0
#define W2_OFF (256*128)
#define W3_OFF (256*128 + 128*128)
#define W_TOTAL (256*128 + 2*128*128)

// smem: W1a | W1b | W2 | W3 | act0 | act1 | sIdx[256i] | sW4[128f] | sBias[384f] | sPart[512f]
#define SW1A_OFF 0
#define SW1B_OFF TILE_B
#define SW2_OFF  (2 * TILE_B)
#define SW3_OFF  (3 * TILE_B)
#define ACT0_OFF (4 * TILE_B)
#define ACT1_OFF (5 * TILE_B)
#define SIDX_OFF (6 * TILE_B)
#define SW4_OFF  (SIDX_OFF + 1024)
#define SBIAS_OFF (SW4_OFF + 512)
#define SPART_OFF (SBIAS_OFF + 1536)
#define SMEM_BYTES (SPART_OFF + 2048)   // 214016

__device__ __nv_bfloat16 g_xbf[(size_t)MAX_N * 128];
__device__ __nv_bfloat16 g_wbf[W_TOTAL];

// ---------------- prep: fp32 -> bf16, 16B stores ----------------
__global__ void cvt_x_kernel(const float* __restrict__ x, int n8) {
    int i = blockIdx.x * blockDim.x + threadIdx.x;
    if (i >= n8) return;
    float4 v0 = ((const float4*)x)[2 * i];
    float4 v1 = ((const float4*)x)[2 * i + 1];
    __nv_bfloat162 p0 = __floats2bfloat162_rn(v0.x, v0.y);
    __nv_bfloat162 p1 = __floats2bfloat162_rn(v0.z, v0.w);
    __nv_bfloat162 p2 = __floats2bfloat162_rn(v1.x, v1.y);
    __nv_bfloat162 p3 = __floats2bfloat162_rn(v1.z, v1.w);
    uint4 o;
    o.x = *(unsigned*)&p0; o.y = *(unsigned*)&p1;
    o.z = *(unsigned*)&p2; o.w = *(unsigned*)&p3;
    ((uint4*)g_xbf)[i] = o;
}
__global__ void cvt_w_kernel(const float* __restrict__ W1,
                             const float* __restrict__ W2,
                             const float* __restrict__ W3) {
    int i = blockIdx.x * blockDim.x + threadIdx.x;
    if (i >= W_TOTAL / 8) return;
    int e = i * 8;
    const float* src = (e < W2_OFF) ? (W1 + e)
                     : (e < W3_OFF) ? (W2 + (e - W2_OFF))
                                    : (W3 + (e - W3_OFF));
    float4 v0 = ((const float4*)src)[0];
    float4 v1 = ((const float4*)src)[1];
    __nv_bfloat162 p0 = __floats2bfloat162_rn(v0.x, v0.y);
    __nv_bfloat162 p1 = __floats2bfloat162_rn(v0.z, v0.w);
    __nv_bfloat162 p2 = __floats2bfloat162_rn(v1.x, v1.y);
    __nv_bfloat162 p3 = __floats2bfloat162_rn(v1.z, v1.w);
    uint4 o;
    o.x = *(unsigned*)&p0; o.y = *(unsigned*)&p1;
    o.z = *(unsigned*)&p2; o.w = *(unsigned*)&p3;
    ((uint4*)g_wbf)[i] = o;
}

// ---------------- async copy + mma helpers ----------------
__device__ __forceinline__ void cp16(unsigned dst, const void* src) {
    asm volatile("cp.async.ca.shared.global [%0], [%1], 16;" :: "r"(dst), "l"(src));
}
#define CP_COMMIT() asm volatile("cp.async.commit_group;" ::: "memory")
#define CP_WAIT(n)  asm volatile("cp.async.wait_group %0;" :: "n"(n) : "memory")
#define HALF_BAR(id) asm volatile("bar.sync %0, 128;" :: "r"(id) : "memory")

__device__ __forceinline__ void ldsm_x4(unsigned* r, unsigned addr) {
    asm volatile("ldmatrix.sync.aligned.m8n8.x4.shared.b16 {%0,%1,%2,%3}, [%4];"
        : "=r"(r[0]), "=r"(r[1]), "=r"(r[2]), "=r"(r[3]) : "r"(addr));
}
__device__ __forceinline__ void ldsm_x4_t(unsigned* r, unsigned addr) {
    asm volatile("ldmatrix.sync.aligned.m8n8.x4.trans.shared.b16 {%0,%1,%2,%3}, [%4];"
        : "=r"(r[0]), "=r"(r[1]), "=r"(r[2]), "=r"(r[3]) : "r"(addr));
}
__device__ __forceinline__ void mma_bf16(float* c, const unsigned* a, const unsigned* b) {
    asm volatile(
        "mma.sync.aligned.m16n8k16.row.col.f32.bf16.bf16.f32 "
        "{%0,%1,%2,%3},{%4,%5,%6,%7},{%8,%9},{%0,%1,%2,%3};"
        : "+f"(c[0]), "+f"(c[1]), "+f"(c[2]), "+f"(c[3])
        : "r"(a[0]), "r"(a[1]), "r"(a[2]), "r"(a[3]), "r"(b[0]), "r"(b[1]));
}

__global__ void __launch_bounds__(THREADS, 1)
edgepred_persist_kernel(
    const int* __restrict__ ei,
    const float* __restrict__ b1, const float* __restrict__ b2,
    const float* __restrict__ b3,
    const float* __restrict__ W4, const float* __restrict__ b4,
    float* __restrict__ out, int E, int N, int nTiles)
{
    extern __shared__ char smem[];
    int*   sIdx  = (int*)(smem + SIDX_OFF);
    float* sW4   = (float*)(smem + SW4_OFF);
    float* sBias = (float*)(smem + SBIAS_OFF);
    float* sPart = (float*)(smem + SPART_OFF);

    const int tid    = threadIdx.x;
    const int lane   = tid & 31;
    const int wid    = tid >> 5;
    const int warp_m = wid >> 2;     // tid<128 <=> warp_m==0
    const int warp_n = wid & 3;
    const int qid    = lane >> 2;
    const int tig    = lane & 3;
    const int half   = (tid < 128) ? 0 : 1;
    const int hr     = tid & 127;

    const unsigned smem_u = (unsigned)__cvta_generic_to_shared(smem);

    // ---- loaders ----
    const int halfw = lane >> 4;
    const int l16   = lane & 15;
    auto load_act = [&](const int* idxs, unsigned dst_u) {
        #pragma unroll
        for (int r = 0; r < 8; ++r) {
            int row = wid * 2 + halfw + r * 16;
            int node = idxs[row];
            cp16(dst_u + row * ROWB + l16 * 16,
                 (const char*)(g_xbf + (size_t)node * 128) + l16 * 16);
        }
    };
    auto load_w = [&](const __nv_bfloat16* W, unsigned dst_u) {
        #pragma unroll
        for (int r = 0; r < 8; ++r) {
            int row = wid * 2 + halfw + r * 16;
            cp16(dst_u + row * ROWB + l16 * 16,
                 (const char*)(W + row * 128) + l16 * 16);
        }
    };

    // ---- LDSM local offsets ----
    const int sub = lane >> 3;
    const int r8  = lane & 7;
    const unsigned aLocal = (unsigned)((((sub & 1) * 8 + r8) * SAB + (sub >> 1) * 8) * 2);
    const unsigned bLocal = (unsigned)((((sub & 1) * 8 + r8) * SAB + warp_n * 32 + (sub >> 1) * 8) * 2);

    float acc[4][4][4];
    auto zero_acc = [&]() {
        #pragma unroll
        for (int mt = 0; mt < 4; ++mt)
            #pragma unroll
            for (int nt = 0; nt < 4; ++nt)
                #pragma unroll
                for (int i = 0; i < 4; ++i) acc[mt][nt][i] = 0.f;
    };

    auto run_mma = [&](unsigned actU, unsigned wU) {
        const unsigned aBase = actU + aLocal;
        const unsigned bBase = wU + bLocal;
        #pragma unroll
        for (int kt = 0; kt < 8; ++kt) {
            unsigned a[4][4], b[2][4];
            #pragma unroll
            for (int mt = 0; mt < 4; ++mt)
                ldsm_x4(a[mt], aBase + (unsigned)((warp_m * 64 + mt * 16) * SAB + kt * 16) * 2);
            #pragma unroll
            for (int ntp = 0; ntp < 2; ++ntp)
                ldsm_x4_t(b[ntp], bBase + (unsigned)(kt * 16 * SAB + ntp * 16) * 2);
            #pragma unroll
            for (int mt = 0; mt < 4; ++mt)
                #pragma unroll
                for (int nt = 0; nt < 4; ++nt)
                    mma_bf16(acc[mt][nt], a[mt], &b[nt >> 1][(nt & 1) * 2]);
        }
    };

    auto epilogue = [&](__nv_bfloat16* base, const float* __restrict__ bias) {
        #pragma unroll
        for (int mt = 0; mt < 4; ++mt) {
            int row = warp_m * 64 + mt * 16 + qid;
            #pragma unroll
            for (int nt = 0; nt < 4; ++nt) {
                int col = warp_n * 32 + nt * 8 + 2 * tig;
                float bb0 = bias[col];
                float bb1 = bias[col + 1];
                float v0 = fmaxf(acc[mt][nt][0] + bb0, 0.f);
                float v1 = fmaxf(acc[mt][nt][1] + bb1, 0.f);
                float v2 = fmaxf(acc[mt][nt][2] + bb0, 0.f);
                float v3 = fmaxf(acc[mt][nt][3] + bb1, 0.f);
                *(__nv_bfloat162*)(base + row * SAB + col)       = __floats2bfloat162_rn(v0, v1);
                *(__nv_bfloat162*)(base + (row + 8) * SAB + col) = __floats2bfloat162_rn(v2, v3);
            }
        }
    };

    auto clamp_idx = [&](long long e, int h) -> int {
        int idx = 0;
        if (e < E) idx = ei[(long long)h * E + e];
        if (idx < 0)  idx = 0;
        if (idx >= N) idx = N - 1;
        return idx;
    };

    // ======== prologue ========
    load_w(g_wbf + W1_OFF,             smem_u + SW1A_OFF);
    load_w(g_wbf + W1_OFF + 128 * 128, smem_u + SW1B_OFF);
    load_w(g_wbf + W2_OFF,             smem_u + SW2_OFF);
    load_w(g_wbf + W3_OFF,             smem_u + SW3_OFF);
    CP_COMMIT();                                        // Gw

    int t0 = blockIdx.x;
    if (t0 >= nTiles) return;
    sIdx[half * 128 + hr] = clamp_idx((long long)t0 * TILE_M + hr, half);
    if (tid < 128) {
        sW4[tid]         = W4[tid];
        sBias[tid]       = b1[tid];
        sBias[128 + tid] = b2[tid];
        sBias[256 + tid] = b3[tid];
    }
    __syncthreads();

    unsigned xiU = smem_u + ACT0_OFF;
    unsigned xjU = smem_u + ACT1_OFF;
    __nv_bfloat16* xiP = (__nv_bfloat16*)(smem + ACT0_OFF);

    load_act(sIdx, xiU);       CP_COMMIT();             // Gxi(t0)
    load_act(sIdx + 128, xjU); CP_COMMIT();             // Gxj(t0)

    const float b4v = __ldg(b4);

    // ======== persistent tile loop ========
    for (int t = t0; t < nTiles; t += gridDim.x) {
        const long long tile0 = (long long)t * TILE_M;
        const int tn = t + gridDim.x;
        const bool hasNext = tn < nTiles;

        CP_WAIT(1);                    // x_i(t) (+weights on first iter) done
        __syncthreads();
        zero_acc();
        run_mma(xiU, smem_u + SW1A_OFF);        // L1A

        int nidx = 0;                  // prefetch next tile's indices (LDG under MMA tail)
        if (hasNext) nidx = clamp_idx((long long)tn * TILE_M + hr, half);

        CP_WAIT(0);                    // x_j(t) done
        __syncthreads();
        run_mma(xjU, smem_u + SW1B_OFF);        // L1B (accumulate)
        if (hasNext) sIdx[half * 128 + hr] = nidx;
        __syncthreads();               // L1B reads done; idx(t+1) visible

        if (hasNext) { load_act(sIdx, xjU); CP_COMMIT(); }   // x_i(t+1) -> freed xj buffer

        epilogue(xiP, sBias);          // h1 -> xi buffer (own half)
        HALF_BAR(1 + warp_m);
        zero_acc();
        run_mma(xiU, smem_u + SW2_OFF);         // L2
        __syncthreads();               // L2 reads of xi buffer done

        epilogue(xiP, sBias + 128);    // h2 -> xi buffer (own half)
        HALF_BAR(1 + warp_m);
        zero_acc();
        run_mma(xiU, smem_u + SW3_OFF);         // L3

        // L4 from registers: relu(acc + b3) . W4, quad-reduce
        #pragma unroll
        for (int mt = 0; mt < 4; ++mt) {
            float z0 = 0.f, z1 = 0.f;
            #pragma unroll
            for (int nt = 0; nt < 4; ++nt) {
                int col = warp_n * 32 + nt * 8 + 2 * tig;
                float bb0 = sBias[256 + col], bb1 = sBias[256 + col + 1];
                float w0  = sW4[col],         w1  = sW4[col + 1];
                z0 += fmaxf(acc[mt][nt][0] + bb0, 0.f) * w0
                    + fmaxf(acc[mt][nt][1] + bb1, 0.f) * w1;
                z1 += fmaxf(acc[mt][nt][2] + bb0, 0.f) * w0
                    + fmaxf(acc[mt][nt][3] + bb1, 0.f) * w1;
            }
            z0 += __shfl_xor_sync(0xFFFFFFFF, z0, 1);
            z0 += __shfl_xor_sync(0xFFFFFFFF, z0, 2);
            z1 += __shfl_xor_sync(0xFFFFFFFF, z1, 1);
            z1 += __shfl_xor_sync(0xFFFFFFFF, z1, 2);
            if (tig == 0) {
                int row = warp_m * 64 + mt * 16 + qid;
                sPart[warp_n * 128 + row]     = z0;
                sPart[warp_n * 128 + row + 8] = z1;
            }
        }
        __syncthreads();               // sPart ready; L3 reads of xi buffer done

        if (hasNext) { load_act(sIdx + 128, xiU); CP_COMMIT(); }  // x_j(t+1) -> freed xi buffer

        if (tid < 128) {
            long long e = tile0 + tid;
            if (e < E) {
                float z = sPart[tid] + sPart[128 + tid] + sPart[256 + tid]
                        + sPart[384 + tid] + b4v;
                out[e] = 1.f / (1.f + expf(-z));
            }
        }

        // swap buffers: x_i(t+1) now sits where x_j(t) was
        unsigned tu = xiU; xiU = xjU; xjU = tu;
        xiP = (__nv_bfloat16*)(smem + (xiU - smem_u));
    }
}

extern "C" void kernel_launch(void* const* d_in, const int* in_sizes, int n_in,
                              void* d_out, int out_size)
{
    const float* x  = (const float*)d_in[0];
    const int*   ei = (const int*)d_in[1];
    const float* W1 = (const float*)d_in[2];
    const float* b1 = (const float*)d_in[3];
    const float* W2 = (const float*)d_in[4];
    const float* b2 = (const float*)d_in[5];
    const float* W3 = (const float*)d_in[6];
    const float* b3 = (const float*)d_in[7];
    const float* W4 = (const float*)d_in[8];
    const float* b4 = (const float*)d_in[9];
    float* out = (float*)d_out;

    int E = in_sizes[1] / 2;
    int N = in_sizes[0] / 128;
    if (N > MAX_N) N = MAX_N;

    int n8 = N * 16;
    cvt_x_kernel<<<(n8 + 511) / 512, 512>>>(x, n8);
    cvt_w_kernel<<<(W_TOTAL / 8 + 255) / 256, 256>>>(W1, W2, W3);

    int nTiles = (E + TILE_M - 1) / TILE_M;
    int sms = 148;
    cudaDeviceGetAttribute(&sms, cudaDevAttrMultiProcessorCount, 0);
    int grid = (sms < nTiles) ? sms : nTiles;

    cudaFuncSetAttribute(edgepred_persist_kernel,
                         cudaFuncAttributeMaxDynamicSharedMemorySize, SMEM_BYTES);
    edgepred_persist_kernel<<<grid, THREADS, SMEM_BYTES>>>(
        ei, b1, b2, b3, W4, b4, out, E, N, nTiles);
}

// round 12
// speedup vs baseline: 1.0334x; 1.0334x over previous
#include <cuda_runtime.h>
#include <cuda_bf16.h>
#include <math.h>

#define TILE_M 128
#define THREADS 256
#define SAB 136                 // bf16 per smem row (272B) -> conflict-free LDSM
#define ROWB (SAB * 2)
#define TILE_B (128 * ROWB)

#define MAX_N 100096
#define W1_OFF 0
#define W2_OFF (256*128)
#define W3_OFF (256*128 + 128*128)
#define W_TOTAL (256*128 + 2*128*128)

#define SA_OFF   0
#define SB0_OFF  TILE_B
#define SB1_OFF  (2 * TILE_B)
#define SIDX_OFF (3 * TILE_B)
#define SW4_OFF  (SIDX_OFF + 1024)
#define SBIAS_OFF (SW4_OFF + 512)
#define SPART_OFF (SBIAS_OFF + 1536)
#define SMEM_BYTES (SPART_OFF + 2048)

__device__ __nv_bfloat16 g_xbf[(size_t)MAX_N * 128];
__device__ __nv_bfloat16 g_wbf[W_TOTAL];

// ---------------- prep: fp32 -> bf16 (merged, 16B stores) ----------------
__global__ void cvt_all_kernel(const float* __restrict__ x,
                               const float* __restrict__ W1,
                               const float* __restrict__ W2,
                               const float* __restrict__ W3, int n8) {
    int i = blockIdx.x * blockDim.x + threadIdx.x;
    const float* src;
    uint4* dst;
    if (i < n8) {
        src = x + i * 8;
        dst = ((uint4*)g_xbf) + i;
    } else {
        int j = i - n8;
        if (j >= W_TOTAL / 8) return;
        int e = j * 8;
        src = (e < W2_OFF) ? (W1 + e)
            : (e < W3_OFF) ? (W2 + (e - W2_OFF))
                           : (W3 + (e - W3_OFF));
        dst = ((uint4*)g_wbf) + j;
    }
    float4 v0 = ((const float4*)src)[0];
    float4 v1 = ((const float4*)src)[1];
    __nv_bfloat162 p0 = __floats2bfloat162_rn(v0.x, v0.y);
    __nv_bfloat162 p1 = __floats2bfloat162_rn(v0.z, v0.w);
    __nv_bfloat162 p2 = __floats2bfloat162_rn(v1.x, v1.y);
    __nv_bfloat162 p3 = __floats2bfloat162_rn(v1.z, v1.w);
    uint4 o;
    o.x = *(unsigned*)&p0; o.y = *(unsigned*)&p1;
    o.z = *(unsigned*)&p2; o.w = *(unsigned*)&p3;
    *dst = o;
}

// ---------------- async copy + mma helpers ----------------
__device__ __forceinline__ void cp16(unsigned dst, const void* src) {
    asm volatile("cp.async.ca.shared.global [%0], [%1], 16;" :: "r"(dst), "l"(src));
}
#define CP_COMMIT() asm volatile("cp.async.commit_group;" ::: "memory")
#define CP_WAIT(n)  asm volatile("cp.async.wait_group %0;" :: "n"(n) : "memory")
#define HALF_BAR(id) asm volatile("bar.sync %0, 128;" :: "r"(id) : "memory")

__device__ __forceinline__ void ldsm_x4(unsigned* r, unsigned addr) {
    asm volatile("ldmatrix.sync.aligned.m8n8.x4.shared.b16 {%0,%1,%2,%3}, [%4];"
        : "=r"(r[0]), "=r"(r[1]), "=r"(r[2]), "=r"(r[3]) : "r"(addr));
}
__device__ __forceinline__ void ldsm_x4_t(unsigned* r, unsigned addr) {
    asm volatile("ldmatrix.sync.aligned.m8n8.x4.trans.shared.b16 {%0,%1,%2,%3}, [%4];"
        : "=r"(r[0]), "=r"(r[1]), "=r"(r[2]), "=r"(r[3]) : "r"(addr));
}
__device__ __forceinline__ void mma_bf16(float* c, const unsigned* a, const unsigned* b) {
    asm volatile(
        "mma.sync.aligned.m16n8k16.row.col.f32.bf16.bf16.f32 "
        "{%0,%1,%2,%3},{%4,%5,%6,%7},{%8,%9},{%0,%1,%2,%3};"
        : "+f"(c[0]), "+f"(c[1]), "+f"(c[2]), "+f"(c[3])
        : "r"(a[0]), "r"(a[1]), "r"(a[2]), "r"(a[3]), "r"(b[0]), "r"(b[1]));
}

__global__ void __launch_bounds__(THREADS, 2)
edgepred_persist2_kernel(
    const int* __restrict__ ei,
    const float* __restrict__ b1, const float* __restrict__ b2,
    const float* __restrict__ b3,
    const float* __restrict__ W4, const float* __restrict__ b4,
    float* __restrict__ out, int E, int N, int nTiles)
{
    extern __shared__ char smem[];
    __nv_bfloat16* sA = (__nv_bfloat16*)(smem + SA_OFF);
    int*   sIdx  = (int*)(smem + SIDX_OFF);
    float* sW4   = (float*)(smem + SW4_OFF);
    float* sBias = (float*)(smem + SBIAS_OFF);
    float* sPart = (float*)(smem + SPART_OFF);

    const int tid    = threadIdx.x;
    const int lane   = tid & 31;
    const int wid    = tid >> 5;
    const int warp_m = wid >> 2;     // tid<128 <=> warp_m==0
    const int warp_n = wid & 3;
    const int qid    = lane >> 2;
    const int tig    = lane & 3;
    const int half   = (tid < 128) ? 0 : 1;
    const int hr     = tid & 127;

    const unsigned smem_u = (unsigned)__cvta_generic_to_shared(smem);
    const unsigned sA_u   = smem_u + SA_OFF;
    const unsigned sB0_u  = smem_u + SB0_OFF;
    const unsigned sB1_u  = smem_u + SB1_OFF;

    const int t0 = blockIdx.x;
    if (t0 >= nTiles) return;

    // ---- loaders ----
    const int halfw = lane >> 4;
    const int l16   = lane & 15;
    auto load_act = [&](const int* idxs, unsigned dst_u) {
        #pragma unroll
        for (int r = 0; r < 8; ++r) {
            int row = wid * 2 + halfw + r * 16;
            int node = idxs[row];
            cp16(dst_u + row * ROWB + l16 * 16,
                 (const char*)(g_xbf + (size_t)node * 128) + l16 * 16);
        }
    };
    auto load_w = [&](const __nv_bfloat16* W, unsigned dst_u) {
        #pragma unroll
        for (int r = 0; r < 8; ++r) {
            int row = wid * 2 + halfw + r * 16;
            cp16(dst_u + row * ROWB + l16 * 16,
                 (const char*)(W + row * 128) + l16 * 16);
        }
    };
    auto clamp_idx = [&](long long e, int h) -> int {
        int idx = 0;
        if (e < E) idx = ei[(long long)h * E + e];
        if (idx < 0)  idx = 0;
        if (idx >= N) idx = N - 1;
        return idx;
    };

    // ---- LDSM local offsets ----
    const int sub = lane >> 3;
    const int r8  = lane & 7;
    const unsigned aBase  = sA_u + (((sub & 1) * 8 + r8) * SAB + (sub >> 1) * 8) * 2;
    const unsigned bLocal = (unsigned)((((sub & 1) * 8 + r8) * SAB + warp_n * 32 + (sub >> 1) * 8) * 2);

    float acc[4][4][4];
    auto zero_acc = [&]() {
        #pragma unroll
        for (int mt = 0; mt < 4; ++mt)
            #pragma unroll
            for (int nt = 0; nt < 4; ++nt)
                #pragma unroll
                for (int i = 0; i < 4; ++i) acc[mt][nt][i] = 0.f;
    };
    auto run_mma = [&](unsigned sBu) {
        const unsigned bBase = sBu + bLocal;
        #pragma unroll
        for (int kt = 0; kt < 8; ++kt) {
            unsigned a[4][4], b[2][4];
            #pragma unroll
            for (int mt = 0; mt < 4; ++mt)
                ldsm_x4(a[mt], aBase + (unsigned)((warp_m * 64 + mt * 16) * SAB + kt * 16) * 2);
            #pragma unroll
            for (int ntp = 0; ntp < 2; ++ntp)
                ldsm_x4_t(b[ntp], bBase + (unsigned)(kt * 16 * SAB + ntp * 16) * 2);
            #pragma unroll
            for (int mt = 0; mt < 4; ++mt)
                #pragma unroll
                for (int nt = 0; nt < 4; ++nt)
                    mma_bf16(acc[mt][nt], a[mt], &b[nt >> 1][(nt & 1) * 2]);
        }
    };
    auto epilogue = [&](const float* __restrict__ bias) {
        #pragma unroll
        for (int mt = 0; mt < 4; ++mt) {
            int row = warp_m * 64 + mt * 16 + qid;
            #pragma unroll
            for (int nt = 0; nt < 4; ++nt) {
                int col = warp_n * 32 + nt * 8 + 2 * tig;
                float bb0 = bias[col];
                float bb1 = bias[col + 1];
                float v0 = fmaxf(acc[mt][nt][0] + bb0, 0.f);
                float v1 = fmaxf(acc[mt][nt][1] + bb1, 0.f);
                float v2 = fmaxf(acc[mt][nt][2] + bb0, 0.f);
                float v3 = fmaxf(acc[mt][nt][3] + bb1, 0.f);
                *(__nv_bfloat162*)(sA + row * SAB + col)       = __floats2bfloat162_rn(v0, v1);
                *(__nv_bfloat162*)(sA + (row + 8) * SAB + col) = __floats2bfloat162_rn(v2, v3);
            }
        }
    };

    // ======== prologue ========
    sIdx[half * 128 + hr] = clamp_idx((long long)t0 * TILE_M + hr, half);
    if (tid < 128) {
        sW4[tid]         = W4[tid];
        sBias[tid]       = b1[tid];
        sBias[128 + tid] = b2[tid];
        sBias[256 + tid] = b3[tid];
    }
    __syncthreads();

    load_act(sIdx, sA_u);                           // P1: x_i(t0) + W1a
    load_w(g_wbf + W1_OFF, sB0_u);
    CP_COMMIT();
    load_w(g_wbf + W1_OFF + 128 * 128, sB1_u);      // P2: W1b
    CP_COMMIT();

    const float b4v = __ldg(b4);

    // ======== persistent tile loop (occ 2) ========
    for (int t = t0; t < nTiles; t += gridDim.x) {
        const long long tile0 = (long long)t * TILE_M;
        const int tn = t + gridDim.x;
        const bool hasNext = tn < nTiles;

        CP_WAIT(1);                     // x_i(t), W1a ready (W1b may fly)
        __syncthreads();
        zero_acc();
        run_mma(sB0_u);                 // L1A (reads sA, sB0)

        int nidx = 0;                   // next tile's indices, LDG under L1A tail
        if (hasNext) nidx = clamp_idx((long long)tn * TILE_M + hr, half);

        __syncthreads();                // sA reads done
        load_act(sIdx + 128, sA_u);     // G3: x_j -> sA
        CP_COMMIT();
        load_w(g_wbf + W2_OFF, sB0_u);  // G4: W2 -> sB0
        CP_COMMIT();

        CP_WAIT(1);                     // W1b + x_j done (W2 may fly)
        __syncthreads();
        run_mma(sB1_u);                 // L1B (accumulate)
        CP_WAIT(0);                     // W2 done (per-thread)
        __syncthreads();                // sB1 free + W2 visible CTA-wide

        if (hasNext) sIdx[half * 128 + hr] = nidx;   // safe: next read after 2 more barriers
        load_w(g_wbf + W3_OFF, sB1_u);  // G5: W3 -> sB1 (overlaps L2)
        CP_COMMIT();
        epilogue(sBias);                // h1 -> sA (own half)
        HALF_BAR(1 + warp_m);
        zero_acc();
        run_mma(sB0_u);                 // L2
        CP_WAIT(0);                     // W3 done
        __syncthreads();                // sB0 free + W3 visible + sA reads done

        if (hasNext) {                  // W1a(t+1) streams under L3
            load_w(g_wbf + W1_OFF, sB0_u);
            CP_COMMIT();
        }
        epilogue(sBias + 128);          // h2 -> sA (own half)
        HALF_BAR(1 + warp_m);
        zero_acc();
        run_mma(sB1_u);                 // L3

        // L4 from registers: relu(acc + b3) . W4, quad-reduce
        #pragma unroll
        for (int mt = 0; mt < 4; ++mt) {
            float z0 = 0.f, z1 = 0.f;
            #pragma unroll
            for (int nt = 0; nt < 4; ++nt) {
                int col = warp_n * 32 + nt * 8 + 2 * tig;
                float bb0 = sBias[256 + col], bb1 = sBias[256 + col + 1];
                float w0  = sW4[col],         w1  = sW4[col + 1];
                z0 += fmaxf(acc[mt][nt][0] + bb0, 0.f) * w0
                    + fmaxf(acc[mt][nt][1] + bb1, 0.f) * w1;
                z1 += fmaxf(acc[mt][nt][2] + bb0, 0.f) * w0
                    + fmaxf(acc[mt][nt][3] + bb1, 0.f) * w1;
            }
            z0 += __shfl_xor_sync(0xFFFFFFFF, z0, 1);
            z0 += __shfl_xor_sync(0xFFFFFFFF, z0, 2);
            z1 += __shfl_xor_sync(0xFFFFFFFF, z1, 1);
            z1 += __shfl_xor_sync(0xFFFFFFFF, z1, 2);
            if (tig == 0) {
                int row = warp_m * 64 + mt * 16 + qid;
                sPart[warp_n * 128 + row]     = z0;
                sPart[warp_n * 128 + row + 8] = z1;
            }
        }
        __syncthreads();                // sPart ready; sA/sB1 free; idx(t+1) visible

        if (hasNext) {
            load_act(sIdx, sA_u);       // P1': x_i(t+1) -> sA
            CP_COMMIT();
            load_w(g_wbf + W1_OFF + 128 * 128, sB1_u);   // P2': W1b(t+1)
            CP_COMMIT();
        }

        if (tid < 128) {
            long long e = tile0 + tid;
            if (e < E) {
                float z = sPart[tid] + sPart[128 + tid] + sPart[256 + tid]
                        + sPart[384 + tid] + b4v;
                out[e] = 1.f / (1.f + __expf(-z));
            }
        }
    }
}

extern "C" void kernel_launch(void* const* d_in, const int* in_sizes, int n_in,
                              void* d_out, int out_size)
{
    const float* x  = (const float*)d_in[0];
    const int*   ei = (const int*)d_in[1];
    const float* W1 = (const float*)d_in[2];
    const float* b1 = (const float*)d_in[3];
    const float* W2 = (const float*)d_in[4];
    const float* b2 = (const float*)d_in[5];
    const float* W3 = (const float*)d_in[6];
    const float* b3 = (const float*)d_in[7];
    const float* W4 = (const float*)d_in[8];
    const float* b4 = (const float*)d_in[9];
    float* out = (float*)d_out;

    int E = in_sizes[1] / 2;
    int N = in_sizes[0] / 128;
    if (N > MAX_N) N = MAX_N;

    int n8 = N * 16;
    int prepTot = n8 + W_TOTAL / 8;
    cvt_all_kernel<<<(prepTot + 511) / 512, 512>>>(x, W1, W2, W3, n8);

    int nTiles = (E + TILE_M - 1) / TILE_M;
    int sms = 148;
    cudaDeviceGetAttribute(&sms, cudaDevAttrMultiProcessorCount, 0);
    int grid = 2 * sms;
    if (grid > nTiles) grid = nTiles;

    cudaFuncSetAttribute(edgepred_persist2_kernel,
                         cudaFuncAttributeMaxDynamicSharedMemorySize, SMEM_BYTES);
    edgepred_persist2_kernel<<<grid, THREADS, SMEM_BYTES>>>(
        ei, b1, b2, b3, W4, b4, out, E, N, nTiles);
}

// round 13
// speedup vs baseline: 1.0413x; 1.0077x over previous
#include <cuda_runtime.h>
#include <cuda_bf16.h>
#include <math.h>

#define TILE_M 128
#define THREADS 256
#define SAB 136                 // bf16 per smem row (272B) -> conflict-free LDSM
#define ROWB (SAB * 2)
#define TILE_B (128 * ROWB)

#define MAX_N 100096
#define W1_OFF 0
#define W2_OFF (256*128)
#define W3_OFF (256*128 + 128*128)
#define W_TOTAL (256*128 + 2*128*128)

#define SA_OFF   0
#define SB0_OFF  TILE_B
#define SB1_OFF  (2 * TILE_B)
#define SIDX_OFF (3 * TILE_B)
#define SW4_OFF  (SIDX_OFF + 1024)
#define SBIAS_OFF (SW4_OFF + 512)
#define SPART_OFF (SBIAS_OFF + 1536)
#define SNEXT_OFF (SPART_OFF + 2048)
#define SMEM_BYTES (SNEXT_OFF + 64)

__device__ __nv_bfloat16 g_xbf[(size_t)MAX_N * 128];
__device__ __nv_bfloat16 g_wbf[W_TOTAL];
__device__ unsigned g_tile_ctr;

// ---------------- prep: fp32 -> bf16 (merged) + work counter reset ----------------
__global__ void cvt_all_kernel(const float* __restrict__ x,
                               const float* __restrict__ W1,
                               const float* __restrict__ W2,
                               const float* __restrict__ W3, int n8, unsigned ctrInit) {
    int i = blockIdx.x * blockDim.x + threadIdx.x;
    if (i == 0) g_tile_ctr = ctrInit;       // reset every replay (runs before main kernel)
    const float* src;
    uint4* dst;
    if (i < n8) {
        src = x + i * 8;
        dst = ((uint4*)g_xbf) + i;
    } else {
        int j = i - n8;
        if (j >= W_TOTAL / 8) return;
        int e = j * 8;
        src = (e < W2_OFF) ? (W1 + e)
            : (e < W3_OFF) ? (W2 + (e - W2_OFF))
                           : (W3 + (e - W3_OFF));
        dst = ((uint4*)g_wbf) + j;
    }
    float4 v0 = ((const float4*)src)[0];
    float4 v1 = ((const float4*)src)[1];
    __nv_bfloat162 p0 = __floats2bfloat162_rn(v0.x, v0.y);
    __nv_bfloat162 p1 = __floats2bfloat162_rn(v0.z, v0.w);
    __nv_bfloat162 p2 = __floats2bfloat162_rn(v1.x, v1.y);
    __nv_bfloat162 p3 = __floats2bfloat162_rn(v1.z, v1.w);
    uint4 o;
    o.x = *(unsigned*)&p0; o.y = *(unsigned*)&p1;
    o.z = *(unsigned*)&p2; o.w = *(unsigned*)&p3;
    *dst = o;
}

// ---------------- async copy + mma helpers ----------------
__device__ __forceinline__ void cp16(unsigned dst, const void* src) {
    asm volatile("cp.async.ca.shared.global [%0], [%1], 16;" :: "r"(dst), "l"(src));
}
#define CP_COMMIT() asm volatile("cp.async.commit_group;" ::: "memory")
#define CP_WAIT(n)  asm volatile("cp.async.wait_group %0;" :: "n"(n) : "memory")
#define HALF_BAR(id) asm volatile("bar.sync %0, 128;" :: "r"(id) : "memory")

__device__ __forceinline__ void ldsm_x4(unsigned* r, unsigned addr) {
    asm volatile("ldmatrix.sync.aligned.m8n8.x4.shared.b16 {%0,%1,%2,%3}, [%4];"
        : "=r"(r[0]), "=r"(r[1]), "=r"(r[2]), "=r"(r[3]) : "r"(addr));
}
__device__ __forceinline__ void ldsm_x4_t(unsigned* r, unsigned addr) {
    asm volatile("ldmatrix.sync.aligned.m8n8.x4.trans.shared.b16 {%0,%1,%2,%3}, [%4];"
        : "=r"(r[0]), "=r"(r[1]), "=r"(r[2]), "=r"(r[3]) : "r"(addr));
}
__device__ __forceinline__ void mma_bf16(float* c, const unsigned* a, const unsigned* b) {
    asm volatile(
        "mma.sync.aligned.m16n8k16.row.col.f32.bf16.bf16.f32 "
        "{%0,%1,%2,%3},{%4,%5,%6,%7},{%8,%9},{%0,%1,%2,%3};"
        : "+f"(c[0]), "+f"(c[1]), "+f"(c[2]), "+f"(c[3])
        : "r"(a[0]), "r"(a[1]), "r"(a[2]), "r"(a[3]), "r"(b[0]), "r"(b[1]));
}

__global__ void __launch_bounds__(THREADS, 2)
edgepred_steal_kernel(
    const int* __restrict__ ei,
    const float* __restrict__ b1, const float* __restrict__ b2,
    const float* __restrict__ b3,
    const float* __restrict__ W4, const float* __restrict__ b4,
    float* __restrict__ out, int E, int N, int nTiles)
{
    extern __shared__ char smem[];
    __nv_bfloat16* sA = (__nv_bfloat16*)(smem + SA_OFF);
    int*   sIdx  = (int*)(smem + SIDX_OFF);
    float* sW4   = (float*)(smem + SW4_OFF);
    float* sBias = (float*)(smem + SBIAS_OFF);
    float* sPart = (float*)(smem + SPART_OFF);
    int*   sNext = (int*)(smem + SNEXT_OFF);

    const int tid    = threadIdx.x;
    const int lane   = tid & 31;
    const int wid    = tid >> 5;
    const int warp_m = wid >> 2;     // tid<128 <=> warp_m==0
    const int warp_n = wid & 3;
    const int qid    = lane >> 2;
    const int tig    = lane & 3;
    const int half   = (tid < 128) ? 0 : 1;
    const int hr     = tid & 127;

    const unsigned smem_u = (unsigned)__cvta_generic_to_shared(smem);
    const unsigned sA_u   = smem_u + SA_OFF;
    const unsigned sB0_u  = smem_u + SB0_OFF;
    const unsigned sB1_u  = smem_u + SB1_OFF;

    int t = blockIdx.x;
    if (t >= nTiles) return;

    // ---- loaders ----
    const int halfw = lane >> 4;
    const int l16   = lane & 15;
    auto load_act = [&](const int* idxs, unsigned dst_u) {
        #pragma unroll
        for (int r = 0; r < 8; ++r) {
            int row = wid * 2 + halfw + r * 16;
            int node = idxs[row];
            cp16(dst_u + row * ROWB + l16 * 16,
                 (const char*)(g_xbf + (size_t)node * 128) + l16 * 16);
        }
    };
    auto load_w = [&](const __nv_bfloat16* W, unsigned dst_u) {
        #pragma unroll
        for (int r = 0; r < 8; ++r) {
            int row = wid * 2 + halfw + r * 16;
            cp16(dst_u + row * ROWB + l16 * 16,
                 (const char*)(W + row * 128) + l16 * 16);
        }
    };
    auto clamp_idx = [&](long long e, int h) -> int {
        int idx = 0;
        if (e < E) idx = ei[(long long)h * E + e];
        if (idx < 0)  idx = 0;
        if (idx >= N) idx = N - 1;
        return idx;
    };

    // ---- LDSM local offsets ----
    const int sub = lane >> 3;
    const int r8  = lane & 7;
    const unsigned aBase  = sA_u + (((sub & 1) * 8 + r8) * SAB + (sub >> 1) * 8) * 2;
    const unsigned bLocal = (unsigned)((((sub & 1) * 8 + r8) * SAB + warp_n * 32 + (sub >> 1) * 8) * 2);

    float acc[4][4][4];
    // initialize accumulators with the layer bias (replaces zero_acc + epilogue bias add)
    auto acc_init = [&](const float* __restrict__ bias) {
        #pragma unroll
        for (int nt = 0; nt < 4; ++nt) {
            int col = warp_n * 32 + nt * 8 + 2 * tig;
            float bb0 = bias[col];
            float bb1 = bias[col + 1];
            #pragma unroll
            for (int mt = 0; mt < 4; ++mt) {
                acc[mt][nt][0] = bb0; acc[mt][nt][1] = bb1;
                acc[mt][nt][2] = bb0; acc[mt][nt][3] = bb1;
            }
        }
    };
    auto run_mma = [&](unsigned sBu) {
        const unsigned bBase = sBu + bLocal;
        #pragma unroll
        for (int kt = 0; kt < 8; ++kt) {
            unsigned a[4][4], b[2][4];
            #pragma unroll
            for (int mt = 0; mt < 4; ++mt)
                ldsm_x4(a[mt], aBase + (unsigned)((warp_m * 64 + mt * 16) * SAB + kt * 16) * 2);
            #pragma unroll
            for (int ntp = 0; ntp < 2; ++ntp)
                ldsm_x4_t(b[ntp], bBase + (unsigned)(kt * 16 * SAB + ntp * 16) * 2);
            #pragma unroll
            for (int mt = 0; mt < 4; ++mt)
                #pragma unroll
                for (int nt = 0; nt < 4; ++nt)
                    mma_bf16(acc[mt][nt], a[mt], &b[nt >> 1][(nt & 1) * 2]);
        }
    };
    auto epilogue = [&]() {   // relu -> bf16 -> sA (bias already in acc)
        #pragma unroll
        for (int mt = 0; mt < 4; ++mt) {
            int row = warp_m * 64 + mt * 16 + qid;
            #pragma unroll
            for (int nt = 0; nt < 4; ++nt) {
                int col = warp_n * 32 + nt * 8 + 2 * tig;
                float v0 = fmaxf(acc[mt][nt][0], 0.f);
                float v1 = fmaxf(acc[mt][nt][1], 0.f);
                float v2 = fmaxf(acc[mt][nt][2], 0.f);
                float v3 = fmaxf(acc[mt][nt][3], 0.f);
                *(__nv_bfloat162*)(sA + row * SAB + col)       = __floats2bfloat162_rn(v0, v1);
                *(__nv_bfloat162*)(sA + (row + 8) * SAB + col) = __floats2bfloat162_rn(v2, v3);
            }
        }
    };

    // ======== prologue ========
    sIdx[half * 128 + hr] = clamp_idx((long long)t * TILE_M + hr, half);
    if (tid < 128) {
        sW4[tid]         = W4[tid];
        sBias[tid]       = b1[tid];
        sBias[128 + tid] = b2[tid];
        sBias[256 + tid] = b3[tid];
    }
    __syncthreads();

    load_act(sIdx, sA_u);                           // P1: x_i(t0) + W1a
    load_w(g_wbf + W1_OFF, sB0_u);
    CP_COMMIT();
    load_w(g_wbf + W1_OFF + 128 * 128, sB1_u);      // P2: W1b
    CP_COMMIT();

    const float b4v = __ldg(b4);

    // ======== persistent work-stealing loop (occ 2) ========
    for (;;) {
        const long long tile0 = (long long)t * TILE_M;

        if (tid == 0) sNext[0] = (int)atomicAdd(&g_tile_ctr, 1u);  // grab next tile

        CP_WAIT(1);                     // x_i(t), W1a ready (W1b may fly)
        __syncthreads();                // + sNext NOT yet needed here
        acc_init(sBias);                // acc = b1
        run_mma(sB0_u);                 // L1A (reads sA, sB0)

        __syncthreads();                // sA reads done; sNext visible
        const int tn = sNext[0];
        const bool hasNext = tn < nTiles;
        int nidx = 0;
        if (hasNext) nidx = clamp_idx((long long)tn * TILE_M + hr, half);  // LDG overlaps below

        load_act(sIdx + 128, sA_u);     // G3: x_j -> sA
        CP_COMMIT();
        load_w(g_wbf + W2_OFF, sB0_u);  // G4: W2 -> sB0
        CP_COMMIT();

        CP_WAIT(1);                     // W1b + x_j done (W2 may fly)
        __syncthreads();
        run_mma(sB1_u);                 // L1B (accumulate)
        CP_WAIT(0);                     // W2 done (per-thread)
        __syncthreads();                // sB1 free + W2 visible CTA-wide

        if (hasNext) sIdx[half * 128 + hr] = nidx;   // next read 2+ barriers away
        load_w(g_wbf + W3_OFF, sB1_u);  // G5: W3 -> sB1 (overlaps L2)
        CP_COMMIT();
        epilogue();                     // h1 -> sA (own half)
        HALF_BAR(1 + warp_m);
        acc_init(sBias + 128);          // acc = b2
        run_mma(sB0_u);                 // L2
        CP_WAIT(0);                     // W3 done
        __syncthreads();                // sB0 free + W3 visible + sA reads done

        if (hasNext) {                  // W1a(t+1) streams under L3
            load_w(g_wbf + W1_OFF, sB0_u);
            CP_COMMIT();
        }
        epilogue();                     // h2 -> sA (own half)
        HALF_BAR(1 + warp_m);
        acc_init(sBias + 256);          // acc = b3
        run_mma(sB1_u);                 // L3

        // L4 from registers: relu(acc) . W4 (bias already in acc), quad-reduce
        #pragma unroll
        for (int mt = 0; mt < 4; ++mt) {
            float z0 = 0.f, z1 = 0.f;
            #pragma unroll
            for (int nt = 0; nt < 4; ++nt) {
                int col = warp_n * 32 + nt * 8 + 2 * tig;
                float w0 = sW4[col], w1 = sW4[col + 1];
                z0 += fmaxf(acc[mt][nt][0], 0.f) * w0
                    + fmaxf(acc[mt][nt][1], 0.f) * w1;
                z1 += fmaxf(acc[mt][nt][2], 0.f) * w0
                    + fmaxf(acc[mt][nt][3], 0.f) * w1;
            }
            z0 += __shfl_xor_sync(0xFFFFFFFF, z0, 1);
            z0 += __shfl_xor_sync(0xFFFFFFFF, z0, 2);
            z1 += __shfl_xor_sync(0xFFFFFFFF, z1, 1);
            z1 += __shfl_xor_sync(0xFFFFFFFF, z1, 2);
            if (tig == 0) {
                int row = warp_m * 64 + mt * 16 + qid;
                sPart[warp_n * 128 + row]     = z0;
                sPart[warp_n * 128 + row + 8] = z1;
            }
        }
        __syncthreads();                // sPart ready; sA/sB1 free; idx(t+1) visible

        if (hasNext) {
            load_act(sIdx, sA_u);       // P1': x_i(t+1) -> sA
            CP_COMMIT();
            load_w(g_wbf + W1_OFF + 128 * 128, sB1_u);   // P2': W1b(t+1)
            CP_COMMIT();
        }

        if (tid < 128) {
            long long e = tile0 + tid;
            if (e < E) {
                float z = sPart[tid] + sPart[128 + tid] + sPart[256 + tid]
                        + sPart[384 + tid] + b4v;
                out[e] = 1.f / (1.f + __expf(-z));
            }
        }

        if (!hasNext) break;
        t = tn;
    }
}

extern "C" void kernel_launch(void* const* d_in, const int* in_sizes, int n_in,
                              void* d_out, int out_size)
{
    const float* x  = (const float*)d_in[0];
    const int*   ei = (const int*)d_in[1];
    const float* W1 = (const float*)d_in[2];
    const float* b1 = (const float*)d_in[3];
    const float* W2 = (const float*)d_in[4];
    const float* b2 = (const float*)d_in[5];
    const float* W3 = (const float*)d_in[6];
    const float* b3 = (const float*)d_in[7];
    const float* W4 = (const float*)d_in[8];
    const float* b4 = (const float*)d_in[9];
    float* out = (float*)d_out;

    int E = in_sizes[1] / 2;
    int N = in_sizes[0] / 128;
    if (N > MAX_N) N = MAX_N;

    int nTiles = (E + TILE_M - 1) / TILE_M;
    int sms = 148;
    cudaDeviceGetAttribute(&sms, cudaDevAttrMultiProcessorCount, 0);
    int grid = 2 * sms;
    if (grid > nTiles) grid = nTiles;

    int n8 = N * 16;
    int prepTot = n8 + W_TOTAL / 8;
    cvt_all_kernel<<<(prepTot + 511) / 512, 512>>>(x, W1, W2, W3, n8, (unsigned)grid);

    cudaFuncSetAttribute(edgepred_steal_kernel,
                         cudaFuncAttributeMaxDynamicSharedMemorySize, SMEM_BYTES);
    edgepred_steal_kernel<<<grid, THREADS, SMEM_BYTES>>>(
        ei, b1, b2, b3, W4, b4, out, E, N, nTiles);
}

// round 14
// speedup vs baseline: 1.0425x; 1.0011x over previous
#include <cuda_runtime.h>
#include <cuda_bf16.h>
#include <math.h>

#define TILE_M 128
#define THREADS 256
#define SAB 136                 // bf16 per smem row (272B) -> conflict-free LDSM
#define ROWB (SAB * 2)
#define TILE_B (128 * ROWB)

#define MAX_N 100096
#define W1_OFF 0
#define W2_OFF (256*128)
#define W3_OFF (256*128 + 128*128)
#define W_TOTAL (256*128 + 2*128*128)

#define SA_OFF   0
#define SB0_OFF  TILE_B
#define SB1_OFF  (2 * TILE_B)
#define SIDX_OFF (3 * TILE_B)
#define SW4_OFF  (SIDX_OFF + 1024)
#define SBIAS_OFF (SW4_OFF + 512)
#define SPART_OFF (SBIAS_OFF + 1536)
#define SNEXT_OFF (SPART_OFF + 2048)
#define SMEM_BYTES (SNEXT_OFF + 64)

__device__ __nv_bfloat16 g_xbf[(size_t)MAX_N * 128];
__device__ __nv_bfloat16 g_wbf[W_TOTAL];
__device__ unsigned g_tile_ctr;

// ---------------- prep: fp32 -> bf16 (merged) + work counter reset ----------------
__global__ void cvt_all_kernel(const float* __restrict__ x,
                               const float* __restrict__ W1,
                               const float* __restrict__ W2,
                               const float* __restrict__ W3, int n8, unsigned ctrInit) {
    int i = blockIdx.x * blockDim.x + threadIdx.x;
    if (i == 0) g_tile_ctr = ctrInit;       // reset every replay (runs before main kernel)
    const float* src;
    uint4* dst;
    if (i < n8) {
        src = x + i * 8;
        dst = ((uint4*)g_xbf) + i;
    } else {
        int j = i - n8;
        if (j >= W_TOTAL / 8) return;
        int e = j * 8;
        src = (e < W2_OFF) ? (W1 + e)
            : (e < W3_OFF) ? (W2 + (e - W2_OFF))
                           : (W3 + (e - W3_OFF));
        dst = ((uint4*)g_wbf) + j;
    }
    float4 v0 = ((const float4*)src)[0];
    float4 v1 = ((const float4*)src)[1];
    __nv_bfloat162 p0 = __floats2bfloat162_rn(v0.x, v0.y);
    __nv_bfloat162 p1 = __floats2bfloat162_rn(v0.z, v0.w);
    __nv_bfloat162 p2 = __floats2bfloat162_rn(v1.x, v1.y);
    __nv_bfloat162 p3 = __floats2bfloat162_rn(v1.z, v1.w);
    uint4 o;
    o.x = *(unsigned*)&p0; o.y = *(unsigned*)&p1;
    o.z = *(unsigned*)&p2; o.w = *(unsigned*)&p3;
    *dst = o;
}

// ---------------- async copy + mma helpers ----------------
__device__ __forceinline__ void cp16(unsigned dst, const void* src) {
    asm volatile("cp.async.ca.shared.global [%0], [%1], 16;" :: "r"(dst), "l"(src));
}
#define CP_COMMIT() asm volatile("cp.async.commit_group;" ::: "memory")
#define CP_WAIT(n)  asm volatile("cp.async.wait_group %0;" :: "n"(n) : "memory")
#define HALF_BAR(id) asm volatile("bar.sync %0, 128;" :: "r"(id) : "memory")

__device__ __forceinline__ void ldsm_x4(unsigned* r, unsigned addr) {
    asm volatile("ldmatrix.sync.aligned.m8n8.x4.shared.b16 {%0,%1,%2,%3}, [%4];"
        : "=r"(r[0]), "=r"(r[1]), "=r"(r[2]), "=r"(r[3]) : "r"(addr));
}
__device__ __forceinline__ void ldsm_x4_t(unsigned* r, unsigned addr) {
    asm volatile("ldmatrix.sync.aligned.m8n8.x4.trans.shared.b16 {%0,%1,%2,%3}, [%4];"
        : "=r"(r[0]), "=r"(r[1]), "=r"(r[2]), "=r"(r[3]) : "r"(addr));
}
__device__ __forceinline__ void mma_bf16(float* c, const unsigned* a, const unsigned* b) {
    asm volatile(
        "mma.sync.aligned.m16n8k16.row.col.f32.bf16.bf16.f32 "
        "{%0,%1,%2,%3},{%4,%5,%6,%7},{%8,%9},{%0,%1,%2,%3};"
        : "+f"(c[0]), "+f"(c[1]), "+f"(c[2]), "+f"(c[3])
        : "r"(a[0]), "r"(a[1]), "r"(a[2]), "r"(a[3]), "r"(b[0]), "r"(b[1]));
}

__global__ void __launch_bounds__(THREADS, 2)
edgepred_steal_kernel(
    const int* __restrict__ ei,
    const float* __restrict__ b1, const float* __restrict__ b2,
    const float* __restrict__ b3,
    const float* __restrict__ W4, const float* __restrict__ b4,
    float* __restrict__ out, int E, int N, int nTiles)
{
    extern __shared__ char smem[];
    __nv_bfloat16* sA = (__nv_bfloat16*)(smem + SA_OFF);
    int*   sIdx  = (int*)(smem + SIDX_OFF);
    float* sW4   = (float*)(smem + SW4_OFF);
    float* sBias = (float*)(smem + SBIAS_OFF);
    float* sPart = (float*)(smem + SPART_OFF);
    int*   sNext = (int*)(smem + SNEXT_OFF);

    const int tid    = threadIdx.x;
    const int lane   = tid & 31;
    const int wid    = tid >> 5;
    const int warp_m = wid >> 2;     // tid<128 <=> warp_m==0
    const int warp_n = wid & 3;
    const int qid    = lane >> 2;
    const int tig    = lane & 3;
    const int half   = (tid < 128) ? 0 : 1;
    const int hr     = tid & 127;

    const unsigned smem_u = (unsigned)__cvta_generic_to_shared(smem);
    const unsigned sA_u   = smem_u + SA_OFF;
    const unsigned sB0_u  = smem_u + SB0_OFF;
    const unsigned sB1_u  = smem_u + SB1_OFF;

    int t = blockIdx.x;
    if (t >= nTiles) return;

    // ---- loaders ----
    const int halfw = lane >> 4;
    const int l16   = lane & 15;
    auto load_act = [&](const int* idxs, unsigned dst_u) {
        #pragma unroll
        for (int r = 0; r < 8; ++r) {
            int row = wid * 2 + halfw + r * 16;
            int node = idxs[row];
            cp16(dst_u + row * ROWB + l16 * 16,
                 (const char*)(g_xbf + (size_t)node * 128) + l16 * 16);
        }
    };
    auto load_w = [&](const __nv_bfloat16* W, unsigned dst_u) {
        #pragma unroll
        for (int r = 0; r < 8; ++r) {
            int row = wid * 2 + halfw + r * 16;
            cp16(dst_u + row * ROWB + l16 * 16,
                 (const char*)(W + row * 128) + l16 * 16);
        }
    };
    auto clamp_idx = [&](long long e, int h) -> int {
        int idx = 0;
        if (e < E) idx = ei[(long long)h * E + e];
        if (idx < 0)  idx = 0;
        if (idx >= N) idx = N - 1;
        return idx;
    };

    // ---- LDSM local offsets ----
    const int sub = lane >> 3;
    const int r8  = lane & 7;
    const unsigned aBase  = sA_u + (((sub & 1) * 8 + r8) * SAB + (sub >> 1) * 8) * 2;
    const unsigned bLocal = (unsigned)((((sub & 1) * 8 + r8) * SAB + warp_n * 32 + (sub >> 1) * 8) * 2);

    float acc[4][4][4];
    auto acc_init = [&](const float* __restrict__ bias) {
        #pragma unroll
        for (int nt = 0; nt < 4; ++nt) {
            int col = warp_n * 32 + nt * 8 + 2 * tig;
            float bb0 = bias[col];
            float bb1 = bias[col + 1];
            #pragma unroll
            for (int mt = 0; mt < 4; ++mt) {
                acc[mt][nt][0] = bb0; acc[mt][nt][1] = bb1;
                acc[mt][nt][2] = bb0; acc[mt][nt][3] = bb1;
            }
        }
    };
    auto run_mma = [&](unsigned sBu) {
        const unsigned bBase = sBu + bLocal;
        #pragma unroll
        for (int kt = 0; kt < 8; ++kt) {
            unsigned a[4][4], b[2][4];
            #pragma unroll
            for (int mt = 0; mt < 4; ++mt)
                ldsm_x4(a[mt], aBase + (unsigned)((warp_m * 64 + mt * 16) * SAB + kt * 16) * 2);
            #pragma unroll
            for (int ntp = 0; ntp < 2; ++ntp)
                ldsm_x4_t(b[ntp], bBase + (unsigned)(kt * 16 * SAB + ntp * 16) * 2);
            #pragma unroll
            for (int mt = 0; mt < 4; ++mt)
                #pragma unroll
                for (int nt = 0; nt < 4; ++nt)
                    mma_bf16(acc[mt][nt], a[mt], &b[nt >> 1][(nt & 1) * 2]);
        }
    };
    auto epilogue = [&]() {   // relu -> bf16 -> sA (bias already in acc)
        #pragma unroll
        for (int mt = 0; mt < 4; ++mt) {
            int row = warp_m * 64 + mt * 16 + qid;
            #pragma unroll
            for (int nt = 0; nt < 4; ++nt) {
                int col = warp_n * 32 + nt * 8 + 2 * tig;
                float v0 = fmaxf(acc[mt][nt][0], 0.f);
                float v1 = fmaxf(acc[mt][nt][1], 0.f);
                float v2 = fmaxf(acc[mt][nt][2], 0.f);
                float v3 = fmaxf(acc[mt][nt][3], 0.f);
                *(__nv_bfloat162*)(sA + row * SAB + col)       = __floats2bfloat162_rn(v0, v1);
                *(__nv_bfloat162*)(sA + (row + 8) * SAB + col) = __floats2bfloat162_rn(v2, v3);
            }
        }
    };

    // ======== prologue ========
    sIdx[half * 128 + hr] = clamp_idx((long long)t * TILE_M + hr, half);
    if (tid < 128) {
        sW4[tid]         = W4[tid];
        sBias[tid]       = b1[tid];
        sBias[128 + tid] = b2[tid];
        sBias[256 + tid] = b3[tid];
    }
    __syncthreads();

    load_act(sIdx, sA_u);                           // P1: x_i(t0) + W1a
    load_w(g_wbf + W1_OFF, sB0_u);
    CP_COMMIT();
    load_w(g_wbf + W1_OFF + 128 * 128, sB1_u);      // P2: W1b
    CP_COMMIT();

    const float b4v = __ldg(b4);

    // ---- anti-phase stagger: second-wave CTAs (co-resident partners) delay
    // ~half an iteration so their MMA phases fill the partner's serial phases.
    // Prefetches above are already in flight, so the spin is itself overlapped.
    if (blockIdx.x >= (gridDim.x >> 1)) {
        long long t0c = clock64();
        while (clock64() - t0c < 13000) { }
    }

    // ======== persistent work-stealing loop (occ 2) ========
    for (;;) {
        const long long tile0 = (long long)t * TILE_M;

        if (tid == 0) sNext[0] = (int)atomicAdd(&g_tile_ctr, 1u);  // grab next tile

        CP_WAIT(1);                     // x_i(t), W1a ready (W1b may fly)
        __syncthreads();
        acc_init(sBias);                // acc = b1
        run_mma(sB0_u);                 // L1A (reads sA, sB0)

        __syncthreads();                // sA reads done; sNext visible
        const int tn = sNext[0];
        const bool hasNext = tn < nTiles;
        int nidx = 0;
        if (hasNext) nidx = clamp_idx((long long)tn * TILE_M + hr, half);

        load_act(sIdx + 128, sA_u);     // G3: x_j -> sA
        CP_COMMIT();
        load_w(g_wbf + W2_OFF, sB0_u);  // G4: W2 -> sB0
        CP_COMMIT();

        CP_WAIT(1);                     // W1b + x_j done (W2 may fly)
        __syncthreads();
        run_mma(sB1_u);                 // L1B (accumulate)
        CP_WAIT(0);                     // W2 done (per-thread)
        __syncthreads();                // sB1 free + W2 visible CTA-wide

        if (hasNext) sIdx[half * 128 + hr] = nidx;   // next read 2+ barriers away
        load_w(g_wbf + W3_OFF, sB1_u);  // G5: W3 -> sB1 (overlaps L2)
        CP_COMMIT();
        epilogue();                     // h1 -> sA (own half)
        HALF_BAR(1 + warp_m);
        acc_init(sBias + 128);          // acc = b2
        run_mma(sB0_u);                 // L2
        CP_WAIT(0);                     // W3 done
        __syncthreads();                // sB0 free + W3 visible + sA reads done

        if (hasNext) {                  // W1a(t+1) streams under L3
            load_w(g_wbf + W1_OFF, sB0_u);
            CP_COMMIT();
        }
        epilogue();                     // h2 -> sA (own half)
        HALF_BAR(1 + warp_m);
        acc_init(sBias + 256);          // acc = b3
        run_mma(sB1_u);                 // L3

        // L4 from registers: relu(acc) . W4 (bias already in acc), quad-reduce
        #pragma unroll
        for (int mt = 0; mt < 4; ++mt) {
            float z0 = 0.f, z1 = 0.f;
            #pragma unroll
            for (int nt = 0; nt < 4; ++nt) {
                int col = warp_n * 32 + nt * 8 + 2 * tig;
                float w0 = sW4[col], w1 = sW4[col + 1];
                z0 += fmaxf(acc[mt][nt][0], 0.f) * w0
                    + fmaxf(acc[mt][nt][1], 0.f) * w1;
                z1 += fmaxf(acc[mt][nt][2], 0.f) * w0
                    + fmaxf(acc[mt][nt][3], 0.f) * w1;
            }
            z0 += __shfl_xor_sync(0xFFFFFFFF, z0, 1);
            z0 += __shfl_xor_sync(0xFFFFFFFF, z0, 2);
            z1 += __shfl_xor_sync(0xFFFFFFFF, z1, 1);
            z1 += __shfl_xor_sync(0xFFFFFFFF, z1, 2);
            if (tig == 0) {
                int row = warp_m * 64 + mt * 16 + qid;
                sPart[warp_n * 128 + row]     = z0;
                sPart[warp_n * 128 + row + 8] = z1;
            }
        }
        __syncthreads();                // sPart ready; sA/sB1 free; idx(t+1) visible

        if (hasNext) {
            load_act(sIdx, sA_u);       // P1': x_i(t+1) -> sA
            CP_COMMIT();
            load_w(g_wbf + W1_OFF + 128 * 128, sB1_u);   // P2': W1b(t+1)
            CP_COMMIT();
        }

        if (tid < 128) {
            long long e = tile0 + tid;
            if (e < E) {
                float z = sPart[tid] + sPart[128 + tid] + sPart[256 + tid]
                        + sPart[384 + tid] + b4v;
                out[e] = 1.f / (1.f + __expf(-z));
            }
        }

        if (!hasNext) break;
        t = tn;
    }
}

extern "C" void kernel_launch(void* const* d_in, const int* in_sizes, int n_in,
                              void* d_out, int out_size)
{
    const float* x  = (const float*)d_in[0];
    const int*   ei = (const int*)d_in[1];
    const float* W1 = (const float*)d_in[2];
    const float* b1 = (const float*)d_in[3];
    const float* W2 = (const float*)d_in[4];
    const float* b2 = (const float*)d_in[5];
    const float* W3 = (const float*)d_in[6];
    const float* b3 = (const float*)d_in[7];
    const float* W4 = (const float*)d_in[8];
    const float* b4 = (const float*)d_in[9];
    float* out = (float*)d_out;

    int E = in_sizes[1] / 2;
    int N = in_sizes[0] / 128;
    if (N > MAX_N) N = MAX_N;

    int nTiles = (E + TILE_M - 1) / TILE_M;
    int sms = 148;
    cudaDeviceGetAttribute(&sms, cudaDevAttrMultiProcessorCount, 0);
    int grid = 2 * sms;
    if (grid > nTiles) grid = nTiles;

    int n8 = N * 16;
    int prepTot = n8 + W_TOTAL / 8;
    cvt_all_kernel<<<(prepTot + 511) / 512, 512>>>(x, W1, W2, W3, n8, (unsigned)grid);

    cudaFuncSetAttribute(edgepred_steal_kernel,
                         cudaFuncAttributeMaxDynamicSharedMemorySize, SMEM_BYTES);
    edgepred_steal_kernel<<<grid, THREADS, SMEM_BYTES>>>(
        ei, b1, b2, b3, W4, b4, out, E, N, nTiles);
}

// round 15
// speedup vs baseline: 1.0431x; 1.0006x over previous
#include <cuda_runtime.h>
#include <cuda_bf16.h>
#include <math.h>

#define TILE_M 128
#define THREADS 256
#define SAB 136                 // bf16 per smem row (272B) -> conflict-free LDSM
#define ROWB (SAB * 2)
#define TILE_B (128 * ROWB)

#define MAX_N 100096
#define W1_OFF 0
#define W2_OFF (256*128)
#define W3_OFF (256*128 + 128*128)
#define W_TOTAL (256*128 + 2*128*128)

#define SA_OFF   0
#define SB0_OFF  TILE_B
#define SB1_OFF  (2 * TILE_B)
#define SIDX_OFF (3 * TILE_B)
#define SW4_OFF  (SIDX_OFF + 1024)
#define SBIAS_OFF (SW4_OFF + 512)
#define SPART_OFF (SBIAS_OFF + 1536)
#define SNEXT_OFF (SPART_OFF + 2048)
#define SMEM_BYTES (SNEXT_OFF + 64)

__device__ __nv_bfloat16 g_xbf[(size_t)MAX_N * 128];
__device__ __nv_bfloat16 g_wbf[W_TOTAL];
__device__ unsigned g_tile_ctr;

// ---------------- prep: fp32 -> bf16 (merged) + work counter reset ----------------
__global__ void cvt_all_kernel(const float* __restrict__ x,
                               const float* __restrict__ W1,
                               const float* __restrict__ W2,
                               const float* __restrict__ W3, int n8, unsigned ctrInit) {
    int i = blockIdx.x * blockDim.x + threadIdx.x;
    if (i == 0) g_tile_ctr = ctrInit;       // reset every replay (runs before main kernel)
    const float* src;
    uint4* dst;
    if (i < n8) {
        src = x + i * 8;
        dst = ((uint4*)g_xbf) + i;
    } else {
        int j = i - n8;
        if (j >= W_TOTAL / 8) return;
        int e = j * 8;
        src = (e < W2_OFF) ? (W1 + e)
            : (e < W3_OFF) ? (W2 + (e - W2_OFF))
                           : (W3 + (e - W3_OFF));
        dst = ((uint4*)g_wbf) + j;
    }
    float4 v0 = ((const float4*)src)[0];
    float4 v1 = ((const float4*)src)[1];
    __nv_bfloat162 p0 = __floats2bfloat162_rn(v0.x, v0.y);
    __nv_bfloat162 p1 = __floats2bfloat162_rn(v0.z, v0.w);
    __nv_bfloat162 p2 = __floats2bfloat162_rn(v1.x, v1.y);
    __nv_bfloat162 p3 = __floats2bfloat162_rn(v1.z, v1.w);
    uint4 o;
    o.x = *(unsigned*)&p0; o.y = *(unsigned*)&p1;
    o.z = *(unsigned*)&p2; o.w = *(unsigned*)&p3;
    *dst = o;
}

// ---------------- async copy + mma helpers ----------------
__device__ __forceinline__ void cp16_ca(unsigned dst, const void* src) {
    asm volatile("cp.async.ca.shared.global [%0], [%1], 16;" :: "r"(dst), "l"(src));
}
__device__ __forceinline__ void cp16_cg(unsigned dst, const void* src) {
    asm volatile("cp.async.cg.shared.global [%0], [%1], 16;" :: "r"(dst), "l"(src));
}
#define CP_COMMIT() asm volatile("cp.async.commit_group;" ::: "memory")
#define CP_WAIT(n)  asm volatile("cp.async.wait_group %0;" :: "n"(n) : "memory")
#define HALF_BAR(id) asm volatile("bar.sync %0, 128;" :: "r"(id) : "memory")

__device__ __forceinline__ void ldsm_x4(unsigned* r, unsigned addr) {
    asm volatile("ldmatrix.sync.aligned.m8n8.x4.shared.b16 {%0,%1,%2,%3}, [%4];"
        : "=r"(r[0]), "=r"(r[1]), "=r"(r[2]), "=r"(r[3]) : "r"(addr));
}
__device__ __forceinline__ void ldsm_x4_t(unsigned* r, unsigned addr) {
    asm volatile("ldmatrix.sync.aligned.m8n8.x4.trans.shared.b16 {%0,%1,%2,%3}, [%4];"
        : "=r"(r[0]), "=r"(r[1]), "=r"(r[2]), "=r"(r[3]) : "r"(addr));
}
__device__ __forceinline__ void mma_bf16(float* c, const unsigned* a, const unsigned* b) {
    asm volatile(
        "mma.sync.aligned.m16n8k16.row.col.f32.bf16.bf16.f32 "
        "{%0,%1,%2,%3},{%4,%5,%6,%7},{%8,%9},{%0,%1,%2,%3};"
        : "+f"(c[0]), "+f"(c[1]), "+f"(c[2]), "+f"(c[3])
        : "r"(a[0]), "r"(a[1]), "r"(a[2]), "r"(a[3]), "r"(b[0]), "r"(b[1]));
}

__global__ void __launch_bounds__(THREADS, 2)
edgepred_steal_kernel(
    const int* __restrict__ ei,
    const float* __restrict__ b1, const float* __restrict__ b2,
    const float* __restrict__ b3,
    const float* __restrict__ W4, const float* __restrict__ b4,
    float* __restrict__ out, int E, int N, int nTiles)
{
    extern __shared__ char smem[];
    __nv_bfloat16* sA = (__nv_bfloat16*)(smem + SA_OFF);
    int*   sIdx  = (int*)(smem + SIDX_OFF);
    float* sW4   = (float*)(smem + SW4_OFF);
    float* sBias = (float*)(smem + SBIAS_OFF);
    float* sPart = (float*)(smem + SPART_OFF);
    int*   sNext = (int*)(smem + SNEXT_OFF);

    const int tid    = threadIdx.x;
    const int lane   = tid & 31;
    const int wid    = tid >> 5;
    const int warp_m = wid >> 2;     // tid<128 <=> warp_m==0
    const int warp_n = wid & 3;
    const int qid    = lane >> 2;
    const int tig    = lane & 3;
    const int half   = (tid < 128) ? 0 : 1;
    const int hr     = tid & 127;

    const unsigned smem_u = (unsigned)__cvta_generic_to_shared(smem);
    const unsigned sA_u   = smem_u + SA_OFF;
    const unsigned sB0_u  = smem_u + SB0_OFF;
    const unsigned sB1_u  = smem_u + SB1_OFF;

    int t = blockIdx.x;
    if (t >= nTiles) return;

    // ---- loaders ----
    const int halfw = lane >> 4;
    const int l16   = lane & 15;
    auto load_act = [&](const int* idxs, unsigned dst_u) {
        #pragma unroll
        for (int r = 0; r < 8; ++r) {
            int row = wid * 2 + halfw + r * 16;
            int node = idxs[row];
            cp16_ca(dst_u + row * ROWB + l16 * 16,
                    (const char*)(g_xbf + (size_t)node * 128) + l16 * 16);
        }
    };
    auto load_w = [&](const __nv_bfloat16* W, unsigned dst_u) {
        #pragma unroll
        for (int r = 0; r < 8; ++r) {
            int row = wid * 2 + halfw + r * 16;
            cp16_cg(dst_u + row * ROWB + l16 * 16,       // .cg: no L1 fill for streamed weights
                    (const char*)(W + row * 128) + l16 * 16);
        }
    };
    auto clamp_idx = [&](long long e, int h) -> int {
        int idx = 0;
        if (e < E) idx = ei[(long long)h * E + e];
        if (idx < 0)  idx = 0;
        if (idx >= N) idx = N - 1;
        return idx;
    };

    // ---- LDSM local offsets ----
    const int sub = lane >> 3;
    const int r8  = lane & 7;
    const unsigned aBase  = sA_u + (((sub & 1) * 8 + r8) * SAB + (sub >> 1) * 8) * 2;
    const unsigned bLocal = (unsigned)((((sub & 1) * 8 + r8) * SAB + warp_n * 32 + (sub >> 1) * 8) * 2);

    float acc[4][4][4];
    auto acc_init = [&](const float* __restrict__ bias) {
        #pragma unroll
        for (int nt = 0; nt < 4; ++nt) {
            int col = warp_n * 32 + nt * 8 + 2 * tig;
            float bb0 = bias[col];
            float bb1 = bias[col + 1];
            #pragma unroll
            for (int mt = 0; mt < 4; ++mt) {
                acc[mt][nt][0] = bb0; acc[mt][nt][1] = bb1;
                acc[mt][nt][2] = bb0; acc[mt][nt][3] = bb1;
            }
        }
    };
    auto run_mma = [&](unsigned sBu) {
        const unsigned bBase = sBu + bLocal;
        #pragma unroll
        for (int kt = 0; kt < 8; ++kt) {
            unsigned a[4][4], b[2][4];
            #pragma unroll
            for (int mt = 0; mt < 4; ++mt)
                ldsm_x4(a[mt], aBase + (unsigned)((warp_m * 64 + mt * 16) * SAB + kt * 16) * 2);
            #pragma unroll
            for (int ntp = 0; ntp < 2; ++ntp)
                ldsm_x4_t(b[ntp], bBase + (unsigned)(kt * 16 * SAB + ntp * 16) * 2);
            #pragma unroll
            for (int mt = 0; mt < 4; ++mt)
                #pragma unroll
                for (int nt = 0; nt < 4; ++nt)
                    mma_bf16(acc[mt][nt], a[mt], &b[nt >> 1][(nt & 1) * 2]);
        }
    };
    auto epilogue = [&]() {   // relu -> bf16 -> sA (bias already in acc)
        #pragma unroll
        for (int mt = 0; mt < 4; ++mt) {
            int row = warp_m * 64 + mt * 16 + qid;
            #pragma unroll
            for (int nt = 0; nt < 4; ++nt) {
                int col = warp_n * 32 + nt * 8 + 2 * tig;
                float v0 = fmaxf(acc[mt][nt][0], 0.f);
                float v1 = fmaxf(acc[mt][nt][1], 0.f);
                float v2 = fmaxf(acc[mt][nt][2], 0.f);
                float v3 = fmaxf(acc[mt][nt][3], 0.f);
                *(__nv_bfloat162*)(sA + row * SAB + col)       = __floats2bfloat162_rn(v0, v1);
                *(__nv_bfloat162*)(sA + (row + 8) * SAB + col) = __floats2bfloat162_rn(v2, v3);
            }
        }
    };

    // ======== prologue ========
    sIdx[half * 128 + hr] = clamp_idx((long long)t * TILE_M + hr, half);
    if (tid < 128) {
        sW4[tid]         = W4[tid];
        sBias[tid]       = b1[tid];
        sBias[128 + tid] = b2[tid];
        sBias[256 + tid] = b3[tid];
    }
    __syncthreads();

    load_act(sIdx, sA_u);                           // P1: x_i(t0) + W1a
    load_w(g_wbf + W1_OFF, sB0_u);
    CP_COMMIT();
    load_w(g_wbf + W1_OFF + 128 * 128, sB1_u);      // P2: W1b
    CP_COMMIT();

    const float b4v = __ldg(b4);

    // ======== persistent work-stealing loop (occ 2) ========
    for (;;) {
        const long long tile0 = (long long)t * TILE_M;

        if (tid == 0) sNext[0] = (int)atomicAdd(&g_tile_ctr, 1u);  // grab next tile

        CP_WAIT(1);                     // x_i(t), W1a ready (W1b may fly)
        __syncthreads();
        acc_init(sBias);                // acc = b1
        run_mma(sB0_u);                 // L1A (reads sA, sB0)

        __syncthreads();                // sA reads done; sNext visible
        const int tn = sNext[0];
        const bool hasNext = tn < nTiles;
        int nidx = 0;
        if (hasNext) nidx = clamp_idx((long long)tn * TILE_M + hr, half);

        load_act(sIdx + 128, sA_u);     // G3: x_j -> sA
        CP_COMMIT();
        load_w(g_wbf + W2_OFF, sB0_u);  // G4: W2 -> sB0
        CP_COMMIT();

        CP_WAIT(1);                     // W1b + x_j done (W2 may fly)
        __syncthreads();
        run_mma(sB1_u);                 // L1B (accumulate)
        CP_WAIT(0);                     // W2 done (per-thread)
        __syncthreads();                // sB1 free + W2 visible CTA-wide

        if (hasNext) sIdx[half * 128 + hr] = nidx;   // next read 2+ barriers away
        load_w(g_wbf + W3_OFF, sB1_u);  // G5: W3 -> sB1 (overlaps L2)
        CP_COMMIT();
        epilogue();                     // h1 -> sA (own half)
        HALF_BAR(1 + warp_m);
        acc_init(sBias + 128);          // acc = b2
        run_mma(sB0_u);                 // L2
        CP_WAIT(0);                     // W3 done
        __syncthreads();                // sB0 free + W3 visible + sA reads done

        if (hasNext) {                  // W1a(t+1) streams under L3
            load_w(g_wbf + W1_OFF, sB0_u);
            CP_COMMIT();
        }
        epilogue();                     // h2 -> sA (own half)
        HALF_BAR(1 + warp_m);
        acc_init(sBias + 256);          // acc = b3
        run_mma(sB1_u);                 // L3

        // L4 from registers: relu(acc) . W4 (bias already in acc), quad-reduce
        #pragma unroll
        for (int mt = 0; mt < 4; ++mt) {
            float z0 = 0.f, z1 = 0.f;
            #pragma unroll
            for (int nt = 0; nt < 4; ++nt) {
                int col = warp_n * 32 + nt * 8 + 2 * tig;
                float w0 = sW4[col], w1 = sW4[col + 1];
                z0 += fmaxf(acc[mt][nt][0], 0.f) * w0
                    + fmaxf(acc[mt][nt][1], 0.f) * w1;
                z1 += fmaxf(acc[mt][nt][2], 0.f) * w0
                    + fmaxf(acc[mt][nt][3], 0.f) * w1;
            }
            z0 += __shfl_xor_sync(0xFFFFFFFF, z0, 1);
            z0 += __shfl_xor_sync(0xFFFFFFFF, z0, 2);
            z1 += __shfl_xor_sync(0xFFFFFFFF, z1, 1);
            z1 += __shfl_xor_sync(0xFFFFFFFF, z1, 2);
            if (tig == 0) {
                int row = warp_m * 64 + mt * 16 + qid;
                sPart[warp_n * 128 + row]     = z0;
                sPart[warp_n * 128 + row + 8] = z1;
            }
        }
        __syncthreads();                // sPart ready; sA/sB1 free; idx(t+1) visible

        if (hasNext) {
            load_act(sIdx, sA_u);       // P1': x_i(t+1) -> sA
            CP_COMMIT();
            load_w(g_wbf + W1_OFF + 128 * 128, sB1_u);   // P2': W1b(t+1)
            CP_COMMIT();
        }

        if (tid < 128) {
            long long e = tile0 + tid;
            if (e < E) {
                float z = sPart[tid] + sPart[128 + tid] + sPart[256 + tid]
                        + sPart[384 + tid] + b4v;
                out[e] = 1.f / (1.f + __expf(-z));
            }
        }

        if (!hasNext) break;
        t = tn;
    }
}

extern "C" void kernel_launch(void* const* d_in, const int* in_sizes, int n_in,
                              void* d_out, int out_size)
{
    const float* x  = (const float*)d_in[0];
    const int*   ei = (const int*)d_in[1];
    const float* W1 = (const float*)d_in[2];
    const float* b1 = (const float*)d_in[3];
    const float* W2 = (const float*)d_in[4];
    const float* b2 = (const float*)d_in[5];
    const float* W3 = (const float*)d_in[6];
    const float* b3 = (const float*)d_in[7];
    const float* W4 = (const float*)d_in[8];
    const float* b4 = (const float*)d_in[9];
    float* out = (float*)d_out;

    int E = in_sizes[1] / 2;
    int N = in_sizes[0] / 128;
    if (N > MAX_N) N = MAX_N;

    int nTiles = (E + TILE_M - 1) / TILE_M;
    int sms = 148;
    cudaDeviceGetAttribute(&sms, cudaDevAttrMultiProcessorCount, 0);
    int grid = 2 * sms;
    if (grid > nTiles) grid = nTiles;

    int n8 = N * 16;
    int prepTot = n8 + W_TOTAL / 8;
    cvt_all_kernel<<<(prepTot + 511) / 512, 512>>>(x, W1, W2, W3, n8, (unsigned)grid);

    cudaFuncSetAttribute(edgepred_steal_kernel,
                         cudaFuncAttributeMaxDynamicSharedMemorySize, SMEM_BYTES);
    edgepred_steal_kernel<<<grid, THREADS, SMEM_BYTES>>>(
        ei, b1, b2, b3, W4, b4, out, E, N, nTiles);
}

// round 16
// speedup vs baseline: 1.0753x; 1.0309x over previous
#include <cuda_runtime.h>
#include <cuda_bf16.h>
#include <math.h>

#define TILE_M 128
#define THREADS 256
#define SAB 136                 // bf16 per smem row (272B) -> conflict-free LDSM
#define ROWB (SAB * 2)
#define TILE_B (128 * ROWB)

#define MAX_N 100096
#define W1_OFF 0
#define W2_OFF (256*128)
#define W3_OFF (256*128 + 128*128)
#define W_TOTAL (256*128 + 2*128*128)

#define SA_OFF   0
#define SB0_OFF  TILE_B
#define SB1_OFF  (2 * TILE_B)
#define SIDX_OFF (3 * TILE_B)
#define SW4_OFF  (SIDX_OFF + 1024)
#define SBIAS_OFF (SW4_OFF + 512)
#define SPART_OFF (SBIAS_OFF + 1536)
#define SNEXT_OFF (SPART_OFF + 2048)
#define SMEM_BYTES (SNEXT_OFF + 64)

__device__ __nv_bfloat16 g_xbf[(size_t)MAX_N * 128];
__device__ __nv_bfloat16 g_wbf[W_TOTAL];
__device__ unsigned g_tile_ctr;

// ---------------- prep: fp32 -> bf16 (merged) + work counter reset ----------------
__global__ void cvt_all_kernel(const float* __restrict__ x,
                               const float* __restrict__ W1,
                               const float* __restrict__ W2,
                               const float* __restrict__ W3, int n8, unsigned ctrInit) {
    int i = blockIdx.x * blockDim.x + threadIdx.x;
    if (i == 0) g_tile_ctr = ctrInit;       // reset every replay (runs before main kernel)
    const float* src;
    uint4* dst;
    if (i < n8) {
        src = x + i * 8;
        dst = ((uint4*)g_xbf) + i;
    } else {
        int j = i - n8;
        if (j >= W_TOTAL / 8) return;
        int e = j * 8;
        src = (e < W2_OFF) ? (W1 + e)
            : (e < W3_OFF) ? (W2 + (e - W2_OFF))
                           : (W3 + (e - W3_OFF));
        dst = ((uint4*)g_wbf) + j;
    }
    float4 v0 = ((const float4*)src)[0];
    float4 v1 = ((const float4*)src)[1];
    __nv_bfloat162 p0 = __floats2bfloat162_rn(v0.x, v0.y);
    __nv_bfloat162 p1 = __floats2bfloat162_rn(v0.z, v0.w);
    __nv_bfloat162 p2 = __floats2bfloat162_rn(v1.x, v1.y);
    __nv_bfloat162 p3 = __floats2bfloat162_rn(v1.z, v1.w);
    uint4 o;
    o.x = *(unsigned*)&p0; o.y = *(unsigned*)&p1;
    o.z = *(unsigned*)&p2; o.w = *(unsigned*)&p3;
    *dst = o;
}

// ---------------- async copy + mma helpers ----------------
__device__ __forceinline__ void cp16_ca(unsigned dst, const void* src) {
    asm volatile("cp.async.ca.shared.global [%0], [%1], 16;" :: "r"(dst), "l"(src));
}
__device__ __forceinline__ void cp16_cg(unsigned dst, const void* src) {
    asm volatile("cp.async.cg.shared.global [%0], [%1], 16;" :: "r"(dst), "l"(src));
}
#define CP_COMMIT() asm volatile("cp.async.commit_group;" ::: "memory")
#define CP_WAIT(n)  asm volatile("cp.async.wait_group %0;" :: "n"(n) : "memory")
#define HALF_BAR(id) asm volatile("bar.sync %0, 128;" :: "r"(id) : "memory")

__device__ __forceinline__ void ldsm_x4(unsigned* r, unsigned addr) {
    asm volatile("ldmatrix.sync.aligned.m8n8.x4.shared.b16 {%0,%1,%2,%3}, [%4];"
        : "=r"(r[0]), "=r"(r[1]), "=r"(r[2]), "=r"(r[3]) : "r"(addr));
}
__device__ __forceinline__ void ldsm_x4_t(unsigned* r, unsigned addr) {
    asm volatile("ldmatrix.sync.aligned.m8n8.x4.trans.shared.b16 {%0,%1,%2,%3}, [%4];"
        : "=r"(r[0]), "=r"(r[1]), "=r"(r[2]), "=r"(r[3]) : "r"(addr));
}
__device__ __forceinline__ void mma_bf16(float* c, const unsigned* a, const unsigned* b) {
    asm volatile(
        "mma.sync.aligned.m16n8k16.row.col.f32.bf16.bf16.f32 "
        "{%0,%1,%2,%3},{%4,%5,%6,%7},{%8,%9},{%0,%1,%2,%3};"
        : "+f"(c[0]), "+f"(c[1]), "+f"(c[2]), "+f"(c[3])
        : "r"(a[0]), "r"(a[1]), "r"(a[2]), "r"(a[3]), "r"(b[0]), "r"(b[1]));
}

__global__ void __launch_bounds__(THREADS, 2)
edgepred_steal_kernel(
    const int* __restrict__ ei,
    const float* __restrict__ b1, const float* __restrict__ b2,
    const float* __restrict__ b3,
    const float* __restrict__ W4, const float* __restrict__ b4,
    float* __restrict__ out, int E, int N, int nTiles)
{
    extern __shared__ char smem[];
    int*   sIdx  = (int*)(smem + SIDX_OFF);
    float* sW4   = (float*)(smem + SW4_OFF);
    float* sBias = (float*)(smem + SBIAS_OFF);
    float* sPart = (float*)(smem + SPART_OFF);
    int*   sNext = (int*)(smem + SNEXT_OFF);

    const int tid    = threadIdx.x;
    const int lane   = tid & 31;
    const int wid    = tid >> 5;
    const int warp_m = wid >> 2;     // tid<128 <=> warp_m==0
    const int warp_n = wid & 3;
    const int qid    = lane >> 2;
    const int tig    = lane & 3;
    const int half   = (tid < 128) ? 0 : 1;
    const int hr     = tid & 127;

    const unsigned smem_u = (unsigned)__cvta_generic_to_shared(smem);
    const unsigned sA_u   = smem_u + SA_OFF;
    const unsigned sB0_u  = smem_u + SB0_OFF;
    const unsigned sB1_u  = smem_u + SB1_OFF;

    int t = blockIdx.x;
    if (t >= nTiles) return;

    // ---- loaders ----
    const int halfw = lane >> 4;
    const int l16   = lane & 15;
    auto load_act = [&](const int* idxs, unsigned dst_u) {
        #pragma unroll
        for (int r = 0; r < 8; ++r) {
            int row = wid * 2 + halfw + r * 16;
            int node = idxs[row];
            cp16_ca(dst_u + row * ROWB + l16 * 16,
                    (const char*)(g_xbf + (size_t)node * 128) + l16 * 16);
        }
    };
    auto load_w_cg = [&](const __nv_bfloat16* W, unsigned dst_u) {
        #pragma unroll
        for (int r = 0; r < 8; ++r) {
            int row = wid * 2 + halfw + r * 16;
            cp16_cg(dst_u + row * ROWB + l16 * 16,
                    (const char*)(W + row * 128) + l16 * 16);
        }
    };
    auto load_w_ca = [&](const __nv_bfloat16* W, unsigned dst_u) {
        #pragma unroll
        for (int r = 0; r < 8; ++r) {
            int row = wid * 2 + halfw + r * 16;
            cp16_ca(dst_u + row * ROWB + l16 * 16,   // .ca: short-lead W1a wants L1 hits
                    (const char*)(W + row * 128) + l16 * 16);
        }
    };
    auto clamp_idx = [&](long long e, int h) -> int {
        int idx = 0;
        if (e < E) idx = ei[(long long)h * E + e];
        if (idx < 0)  idx = 0;
        if (idx >= N) idx = N - 1;
        return idx;
    };

    // ---- LDSM local offsets ----
    const int sub = lane >> 3;
    const int r8  = lane & 7;
    const unsigned aLocal = (unsigned)((((sub & 1) * 8 + r8) * SAB + (sub >> 1) * 8) * 2);
    const unsigned bLocal = (unsigned)((((sub & 1) * 8 + r8) * SAB + warp_n * 32 + (sub >> 1) * 8) * 2);

    float acc[4][4][4];
    auto acc_init = [&](const float* __restrict__ bias) {
        #pragma unroll
        for (int nt = 0; nt < 4; ++nt) {
            int col = warp_n * 32 + nt * 8 + 2 * tig;
            float bb0 = bias[col];
            float bb1 = bias[col + 1];
            #pragma unroll
            for (int mt = 0; mt < 4; ++mt) {
                acc[mt][nt][0] = bb0; acc[mt][nt][1] = bb1;
                acc[mt][nt][2] = bb0; acc[mt][nt][3] = bb1;
            }
        }
    };
    auto run_mma = [&](unsigned actU, unsigned wU) {
        const unsigned aBase = actU + aLocal;
        const unsigned bBase = wU + bLocal;
        #pragma unroll
        for (int kt = 0; kt < 8; ++kt) {
            unsigned a[4][4], b[2][4];
            #pragma unroll
            for (int mt = 0; mt < 4; ++mt)
                ldsm_x4(a[mt], aBase + (unsigned)((warp_m * 64 + mt * 16) * SAB + kt * 16) * 2);
            #pragma unroll
            for (int ntp = 0; ntp < 2; ++ntp)
                ldsm_x4_t(b[ntp], bBase + (unsigned)(kt * 16 * SAB + ntp * 16) * 2);
            #pragma unroll
            for (int mt = 0; mt < 4; ++mt)
                #pragma unroll
                for (int nt = 0; nt < 4; ++nt)
                    mma_bf16(acc[mt][nt], a[mt], &b[nt >> 1][(nt & 1) * 2]);
        }
    };
    auto epilogue = [&](unsigned dstU) {   // relu -> bf16 -> dst tile (bias already in acc)
        __nv_bfloat16* base = (__nv_bfloat16*)(smem + (dstU - smem_u));
        #pragma unroll
        for (int mt = 0; mt < 4; ++mt) {
            int row = warp_m * 64 + mt * 16 + qid;
            #pragma unroll
            for (int nt = 0; nt < 4; ++nt) {
                int col = warp_n * 32 + nt * 8 + 2 * tig;
                float v0 = fmaxf(acc[mt][nt][0], 0.f);
                float v1 = fmaxf(acc[mt][nt][1], 0.f);
                float v2 = fmaxf(acc[mt][nt][2], 0.f);
                float v3 = fmaxf(acc[mt][nt][3], 0.f);
                *(__nv_bfloat162*)(base + row * SAB + col)       = __floats2bfloat162_rn(v0, v1);
                *(__nv_bfloat162*)(base + (row + 8) * SAB + col) = __floats2bfloat162_rn(v2, v3);
            }
        }
    };

    // ======== prologue: x_i -> sA (G1), W1a -> sB0 (G2), W1b -> sB1 (G3) ========
    sIdx[half * 128 + hr] = clamp_idx((long long)t * TILE_M + hr, half);
    if (tid < 128) {
        sW4[tid]         = W4[tid];
        sBias[tid]       = b1[tid];
        sBias[128 + tid] = b2[tid];
        sBias[256 + tid] = b3[tid];
    }
    __syncthreads();

    load_act(sIdx, sA_u);            CP_COMMIT();
    load_w_ca(g_wbf + W1_OFF, sB0_u); CP_COMMIT();
    load_w_cg(g_wbf + W1_OFF + 128 * 128, sB1_u); CP_COMMIT();

    const float b4v = __ldg(b4);

    // ======== persistent work-stealing loop (occ 2) ========
    // Loop-top state: x_i in sA (long lead), W1a in sB0, W1b in sB1.
    for (;;) {
        const long long tile0 = (long long)t * TILE_M;

        if (tid == 0) sNext[0] = (int)atomicAdd(&g_tile_ctr, 1u);

        CP_WAIT(1);                     // x_i + W1a ready (W1b may fly)
        __syncthreads();
        acc_init(sBias);                // acc = b1
        run_mma(sA_u, sB0_u);           // L1A

        __syncthreads();                // sA, sB0 reads done; sNext visible
        const int tn = sNext[0];
        const bool hasNext = tn < nTiles;
        int nidx = 0;
        if (hasNext) nidx = clamp_idx((long long)tn * TILE_M + hr, half);

        load_act(sIdx + 128, sA_u);     // x_j -> sA
        CP_COMMIT();
        load_w_cg(g_wbf + W2_OFF, sB0_u);  // W2 -> sB0 (overlaps L1B)
        CP_COMMIT();

        CP_WAIT(1);                     // W1b + x_j done (W2 may fly)
        __syncthreads();
        run_mma(sA_u, sB1_u);           // L1B (accumulate)
        CP_WAIT(0);                     // W2 done (per-thread)
        __syncthreads();                // sB1 free + W2 visible CTA-wide

        if (hasNext) sIdx[half * 128 + hr] = nidx;   // read after next full sync
        load_w_cg(g_wbf + W3_OFF, sB1_u);  // W3 -> sB1 (overlaps L2)
        CP_COMMIT();
        epilogue(sA_u);                 // h1 -> sA (own half)
        HALF_BAR(1 + warp_m);
        acc_init(sBias + 128);          // acc = b2
        run_mma(sA_u, sB0_u);           // L2
        CP_WAIT(0);                     // W3 done
        __syncthreads();                // sA free + sB0 free + W3 visible + idx(t+1) visible

        // Long-lead gather: x_i(t+1) -> sA, overlapping h2 epilogue + L3 + L4
        if (hasNext) { load_act(sIdx, sA_u); CP_COMMIT(); }

        epilogue(sB0_u);                // h2 -> sB0 (own half; W2 reads done at sync above)
        HALF_BAR(1 + warp_m);
        acc_init(sBias + 256);          // acc = b3
        run_mma(sB0_u, sB1_u);          // L3: A=h2(sB0), B=W3(sB1)

        // L4 from registers: relu(acc) . W4, quad-reduce
        #pragma unroll
        for (int mt = 0; mt < 4; ++mt) {
            float z0 = 0.f, z1 = 0.f;
            #pragma unroll
            for (int nt = 0; nt < 4; ++nt) {
                int col = warp_n * 32 + nt * 8 + 2 * tig;
                float w0 = sW4[col], w1 = sW4[col + 1];
                z0 += fmaxf(acc[mt][nt][0], 0.f) * w0
                    + fmaxf(acc[mt][nt][1], 0.f) * w1;
                z1 += fmaxf(acc[mt][nt][2], 0.f) * w0
                    + fmaxf(acc[mt][nt][3], 0.f) * w1;
            }
            z0 += __shfl_xor_sync(0xFFFFFFFF, z0, 1);
            z0 += __shfl_xor_sync(0xFFFFFFFF, z0, 2);
            z1 += __shfl_xor_sync(0xFFFFFFFF, z1, 1);
            z1 += __shfl_xor_sync(0xFFFFFFFF, z1, 2);
            if (tig == 0) {
                int row = warp_m * 64 + mt * 16 + qid;
                sPart[warp_n * 128 + row]     = z0;
                sPart[warp_n * 128 + row + 8] = z1;
            }
        }
        __syncthreads();                // sPart ready; sB0/sB1 L3 reads done

        if (hasNext) {                  // short-lead slots: cheap fixed-address weights
            load_w_ca(g_wbf + W1_OFF, sB0_u);             // W1a' (.ca, L1-hot)
            CP_COMMIT();
            load_w_cg(g_wbf + W1_OFF + 128 * 128, sB1_u); // W1b' (long lead to L1B')
            CP_COMMIT();
        }

        if (tid < 128) {
            long long e = tile0 + tid;
            if (e < E) {
                float z = sPart[tid] + sPart[128 + tid] + sPart[256 + tid]
                        + sPart[384 + tid] + b4v;
                out[e] = 1.f / (1.f + __expf(-z));
            }
        }

        if (!hasNext) break;
        t = tn;
    }
}

extern "C" void kernel_launch(void* const* d_in, const int* in_sizes, int n_in,
                              void* d_out, int out_size)
{
    const float* x  = (const float*)d_in[0];
    const int*   ei = (const int*)d_in[1];
    const float* W1 = (const float*)d_in[2];
    const float* b1 = (const float*)d_in[3];
    const float* W2 = (const float*)d_in[4];
    const float* b2 = (const float*)d_in[5];
    const float* W3 = (const float*)d_in[6];
    const float* b3 = (const float*)d_in[7];
    const float* W4 = (const float*)d_in[8];
    const float* b4 = (const float*)d_in[9];
    float* out = (float*)d_out;

    int E = in_sizes[1] / 2;
    int N = in_sizes[0] / 128;
    if (N > MAX_N) N = MAX_N;

    int nTiles = (E + TILE_M - 1) / TILE_M;
    int sms = 148;
    cudaDeviceGetAttribute(&sms, cudaDevAttrMultiProcessorCount, 0);
    int grid = 2 * sms;
    if (grid > nTiles) grid = nTiles;

    int n8 = N * 16;
    int prepTot = n8 + W_TOTAL / 8;
    cvt_all_kernel<<<(prepTot + 511) / 512, 512>>>(x, W1, W2, W3, n8, (unsigned)grid);

    cudaFuncSetAttribute(edgepred_steal_kernel,
                         cudaFuncAttributeMaxDynamicSharedMemorySize, SMEM_BYTES);
    edgepred_steal_kernel<<<grid, THREADS, SMEM_BYTES>>>(
        ei, b1, b2, b3, W4, b4, out, E, N, nTiles);
}

// round 17
// speedup vs baseline: 1.0814x; 1.0057x over previous
#include <cuda_runtime.h>
#include <cuda_bf16.h>
#include <math.h>

#define TILE_M 128
#define THREADS 256
#define SAB 136                 // bf16 per smem row (272B) -> conflict-free LDSM
#define ROWB (SAB * 2)
#define TILE_B (128 * ROWB)

#define MAX_N 100096
#define W1_OFF 0
#define W2_OFF (256*128)
#define W3_OFF (256*128 + 128*128)
#define W_TOTAL (256*128 + 2*128*128)

#define SA_OFF   0
#define SB0_OFF  TILE_B
#define SB1_OFF  (2 * TILE_B)
#define SIDX_OFF (3 * TILE_B)
#define SW4_OFF  (SIDX_OFF + 1024)
#define SBIAS_OFF (SW4_OFF + 512)
#define SPART_OFF (SBIAS_OFF + 1536)
#define SNEXT_OFF (SPART_OFF + 2048)
#define SMEM_BYTES (SNEXT_OFF + 64)

__device__ __nv_bfloat16 g_xbf[(size_t)MAX_N * 128];
__device__ __nv_bfloat16 g_wbf[W_TOTAL];
__device__ unsigned g_tile_ctr;

// ---------------- prep: fp32 -> bf16, 64B/thread, MLP=4, grid-stride ----------------
__device__ __forceinline__ uint4 cvt8(float4 a, float4 b) {
    __nv_bfloat162 p0 = __floats2bfloat162_rn(a.x, a.y);
    __nv_bfloat162 p1 = __floats2bfloat162_rn(a.z, a.w);
    __nv_bfloat162 p2 = __floats2bfloat162_rn(b.x, b.y);
    __nv_bfloat162 p3 = __floats2bfloat162_rn(b.z, b.w);
    uint4 o;
    o.x = *(unsigned*)&p0; o.y = *(unsigned*)&p1;
    o.z = *(unsigned*)&p2; o.w = *(unsigned*)&p3;
    return o;
}
// i indexes 16-float chunks (two uint4 outputs per thread-iter)
__global__ void cvt_all_kernel(const float* __restrict__ x,
                               const float* __restrict__ W1,
                               const float* __restrict__ W2,
                               const float* __restrict__ W3,
                               int n16, int tot16, unsigned ctrInit) {
    int i0 = blockIdx.x * blockDim.x + threadIdx.x;
    if (i0 == 0) g_tile_ctr = ctrInit;      // reset every replay
    for (int i = i0; i < tot16; i += gridDim.x * blockDim.x) {
        const float* src;
        uint4* dst;
        if (i < n16) {
            src = x + (size_t)i * 16;
            dst = ((uint4*)g_xbf) + 2 * i;
        } else {
            int j = i - n16;                 // 16-float chunk within weights
            int e = j * 16;
            src = (e < W2_OFF) ? (W1 + e)
                : (e < W3_OFF) ? (W2 + (e - W2_OFF))
                               : (W3 + (e - W3_OFF));
            dst = ((uint4*)g_wbf) + 2 * j;
        }
        // 4 independent 16B loads -> MLP 4
        float4 v0 = ((const float4*)src)[0];
        float4 v1 = ((const float4*)src)[1];
        float4 v2 = ((const float4*)src)[2];
        float4 v3 = ((const float4*)src)[3];
        dst[0] = cvt8(v0, v1);
        dst[1] = cvt8(v2, v3);
    }
}

// ---------------- async copy + mma helpers ----------------
__device__ __forceinline__ void cp16_ca(unsigned dst, const void* src) {
    asm volatile("cp.async.ca.shared.global [%0], [%1], 16;" :: "r"(dst), "l"(src));
}
__device__ __forceinline__ void cp16_cg(unsigned dst, const void* src) {
    asm volatile("cp.async.cg.shared.global [%0], [%1], 16;" :: "r"(dst), "l"(src));
}
#define CP_COMMIT() asm volatile("cp.async.commit_group;" ::: "memory")
#define CP_WAIT(n)  asm volatile("cp.async.wait_group %0;" :: "n"(n) : "memory")
#define HALF_BAR(id) asm volatile("bar.sync %0, 128;" :: "r"(id) : "memory")

__device__ __forceinline__ void ldsm_x4(unsigned* r, unsigned addr) {
    asm volatile("ldmatrix.sync.aligned.m8n8.x4.shared.b16 {%0,%1,%2,%3}, [%4];"
        : "=r"(r[0]), "=r"(r[1]), "=r"(r[2]), "=r"(r[3]) : "r"(addr));
}
__device__ __forceinline__ void ldsm_x4_t(unsigned* r, unsigned addr) {
    asm volatile("ldmatrix.sync.aligned.m8n8.x4.trans.shared.b16 {%0,%1,%2,%3}, [%4];"
        : "=r"(r[0]), "=r"(r[1]), "=r"(r[2]), "=r"(r[3]) : "r"(addr));
}
__device__ __forceinline__ void mma_bf16(float* c, const unsigned* a, const unsigned* b) {
    asm volatile(
        "mma.sync.aligned.m16n8k16.row.col.f32.bf16.bf16.f32 "
        "{%0,%1,%2,%3},{%4,%5,%6,%7},{%8,%9},{%0,%1,%2,%3};"
        : "+f"(c[0]), "+f"(c[1]), "+f"(c[2]), "+f"(c[3])
        : "r"(a[0]), "r"(a[1]), "r"(a[2]), "r"(a[3]), "r"(b[0]), "r"(b[1]));
}

__global__ void __launch_bounds__(THREADS, 2)
edgepred_steal_kernel(
    const int* __restrict__ ei,
    const float* __restrict__ b1, const float* __restrict__ b2,
    const float* __restrict__ b3,
    const float* __restrict__ W4, const float* __restrict__ b4,
    float* __restrict__ out, int E, int N, int nTiles)
{
    extern __shared__ char smem[];
    int*   sIdx  = (int*)(smem + SIDX_OFF);
    float* sW4   = (float*)(smem + SW4_OFF);
    float* sBias = (float*)(smem + SBIAS_OFF);
    float* sPart = (float*)(smem + SPART_OFF);
    int*   sNext = (int*)(smem + SNEXT_OFF);

    const int tid    = threadIdx.x;
    const int lane   = tid & 31;
    const int wid    = tid >> 5;
    const int warp_m = wid >> 2;     // tid<128 <=> warp_m==0
    const int warp_n = wid & 3;
    const int qid    = lane >> 2;
    const int tig    = lane & 3;
    const int half   = (tid < 128) ? 0 : 1;
    const int hr     = tid & 127;

    const unsigned smem_u = (unsigned)__cvta_generic_to_shared(smem);
    const unsigned sA_u   = smem_u + SA_OFF;
    const unsigned sB0_u  = smem_u + SB0_OFF;
    const unsigned sB1_u  = smem_u + SB1_OFF;

    int t = blockIdx.x;
    if (t >= nTiles) return;

    // ---- loaders ----
    const int halfw = lane >> 4;
    const int l16   = lane & 15;
    auto load_act = [&](const int* idxs, unsigned dst_u) {
        #pragma unroll
        for (int r = 0; r < 8; ++r) {
            int row = wid * 2 + halfw + r * 16;
            int node = idxs[row];
            cp16_ca(dst_u + row * ROWB + l16 * 16,
                    (const char*)(g_xbf + (size_t)node * 128) + l16 * 16);
        }
    };
    auto load_w_cg = [&](const __nv_bfloat16* W, unsigned dst_u) {
        #pragma unroll
        for (int r = 0; r < 8; ++r) {
            int row = wid * 2 + halfw + r * 16;
            cp16_cg(dst_u + row * ROWB + l16 * 16,
                    (const char*)(W + row * 128) + l16 * 16);
        }
    };
    auto load_w_ca = [&](const __nv_bfloat16* W, unsigned dst_u) {
        #pragma unroll
        for (int r = 0; r < 8; ++r) {
            int row = wid * 2 + halfw + r * 16;
            cp16_ca(dst_u + row * ROWB + l16 * 16,
                    (const char*)(W + row * 128) + l16 * 16);
        }
    };
    auto clamp_idx = [&](long long e, int h) -> int {
        int idx = 0;
        if (e < E) idx = ei[(long long)h * E + e];
        if (idx < 0)  idx = 0;
        if (idx >= N) idx = N - 1;
        return idx;
    };

    // ---- LDSM local offsets ----
    const int sub = lane >> 3;
    const int r8  = lane & 7;
    const unsigned aLocal = (unsigned)((((sub & 1) * 8 + r8) * SAB + (sub >> 1) * 8) * 2);
    const unsigned bLocal = (unsigned)((((sub & 1) * 8 + r8) * SAB + warp_n * 32 + (sub >> 1) * 8) * 2);

    float acc[4][4][4];
    auto acc_init = [&](const float* __restrict__ bias) {
        #pragma unroll
        for (int nt = 0; nt < 4; ++nt) {
            int col = warp_n * 32 + nt * 8 + 2 * tig;
            float bb0 = bias[col];
            float bb1 = bias[col + 1];
            #pragma unroll
            for (int mt = 0; mt < 4; ++mt) {
                acc[mt][nt][0] = bb0; acc[mt][nt][1] = bb1;
                acc[mt][nt][2] = bb0; acc[mt][nt][3] = bb1;
            }
        }
    };
    auto run_mma = [&](unsigned actU, unsigned wU) {
        const unsigned aBase = actU + aLocal;
        const unsigned bBase = wU + bLocal;
        #pragma unroll
        for (int kt = 0; kt < 8; ++kt) {
            unsigned a[4][4], b[2][4];
            #pragma unroll
            for (int mt = 0; mt < 4; ++mt)
                ldsm_x4(a[mt], aBase + (unsigned)((warp_m * 64 + mt * 16) * SAB + kt * 16) * 2);
            #pragma unroll
            for (int ntp = 0; ntp < 2; ++ntp)
                ldsm_x4_t(b[ntp], bBase + (unsigned)(kt * 16 * SAB + ntp * 16) * 2);
            #pragma unroll
            for (int mt = 0; mt < 4; ++mt)
                #pragma unroll
                for (int nt = 0; nt < 4; ++nt)
                    mma_bf16(acc[mt][nt], a[mt], &b[nt >> 1][(nt & 1) * 2]);
        }
    };
    auto epilogue = [&](unsigned dstU) {   // relu -> bf16 -> dst tile (bias already in acc)
        __nv_bfloat16* base = (__nv_bfloat16*)(smem + (dstU - smem_u));
        #pragma unroll
        for (int mt = 0; mt < 4; ++mt) {
            int row = warp_m * 64 + mt * 16 + qid;
            #pragma unroll
            for (int nt = 0; nt < 4; ++nt) {
                int col = warp_n * 32 + nt * 8 + 2 * tig;
                float v0 = fmaxf(acc[mt][nt][0], 0.f);
                float v1 = fmaxf(acc[mt][nt][1], 0.f);
                float v2 = fmaxf(acc[mt][nt][2], 0.f);
                float v3 = fmaxf(acc[mt][nt][3], 0.f);
                *(__nv_bfloat162*)(base + row * SAB + col)       = __floats2bfloat162_rn(v0, v1);
                *(__nv_bfloat162*)(base + (row + 8) * SAB + col) = __floats2bfloat162_rn(v2, v3);
            }
        }
    };

    // ======== prologue: x_i -> sA (G1), W1a -> sB0 (G2), W1b -> sB1 (G3) ========
    sIdx[half * 128 + hr] = clamp_idx((long long)t * TILE_M + hr, half);
    if (tid < 128) {
        sW4[tid]         = W4[tid];
        sBias[tid]       = b1[tid];
        sBias[128 + tid] = b2[tid];
        sBias[256 + tid] = b3[tid];
    }
    __syncthreads();

    load_act(sIdx, sA_u);            CP_COMMIT();
    load_w_ca(g_wbf + W1_OFF, sB0_u); CP_COMMIT();
    load_w_cg(g_wbf + W1_OFF + 128 * 128, sB1_u); CP_COMMIT();

    const float b4v = __ldg(b4);

    // ======== persistent work-stealing loop (occ 2) ========
    for (;;) {
        const long long tile0 = (long long)t * TILE_M;

        if (tid == 0) sNext[0] = (int)atomicAdd(&g_tile_ctr, 1u);

        CP_WAIT(1);                     // x_i + W1a ready (W1b may fly)
        __syncthreads();
        acc_init(sBias);                // acc = b1
        run_mma(sA_u, sB0_u);           // L1A

        __syncthreads();                // sA, sB0 reads done; sNext visible
        const int tn = sNext[0];
        const bool hasNext = tn < nTiles;
        int nidx = 0;
        if (hasNext) nidx = clamp_idx((long long)tn * TILE_M + hr, half);

        load_act(sIdx + 128, sA_u);     // x_j -> sA
        CP_COMMIT();
        load_w_cg(g_wbf + W2_OFF, sB0_u);  // W2 -> sB0 (overlaps L1B)
        CP_COMMIT();

        CP_WAIT(1);                     // W1b + x_j done (W2 may fly)
        __syncthreads();
        run_mma(sA_u, sB1_u);           // L1B (accumulate)
        CP_WAIT(0);                     // W2 done (per-thread)
        __syncthreads();                // sB1 free + W2 visible CTA-wide

        if (hasNext) sIdx[half * 128 + hr] = nidx;   // read after next full sync
        load_w_cg(g_wbf + W3_OFF, sB1_u);  // W3 -> sB1 (overlaps L2)
        CP_COMMIT();
        epilogue(sA_u);                 // h1 -> sA (own half)
        HALF_BAR(1 + warp_m);
        acc_init(sBias + 128);          // acc = b2
        run_mma(sA_u, sB0_u);           // L2
        CP_WAIT(0);                     // W3 done
        __syncthreads();                // sA free + sB0 free + W3 visible + idx(t+1) visible

        // Long-lead gather: x_i(t+1) -> sA, overlapping h2 epilogue + L3 + L4
        if (hasNext) { load_act(sIdx, sA_u); CP_COMMIT(); }

        epilogue(sB0_u);                // h2 -> sB0 (own half)
        HALF_BAR(1 + warp_m);
        acc_init(sBias + 256);          // acc = b3
        run_mma(sB0_u, sB1_u);          // L3: A=h2(sB0), B=W3(sB1)

        // L4 from registers: relu(acc) . W4, quad-reduce
        #pragma unroll
        for (int mt = 0; mt < 4; ++mt) {
            float z0 = 0.f, z1 = 0.f;
            #pragma unroll
            for (int nt = 0; nt < 4; ++nt) {
                int col = warp_n * 32 + nt * 8 + 2 * tig;
                float w0 = sW4[col], w1 = sW4[col + 1];
                z0 += fmaxf(acc[mt][nt][0], 0.f) * w0
                    + fmaxf(acc[mt][nt][1], 0.f) * w1;
                z1 += fmaxf(acc[mt][nt][2], 0.f) * w0
                    + fmaxf(acc[mt][nt][3], 0.f) * w1;
            }
            z0 += __shfl_xor_sync(0xFFFFFFFF, z0, 1);
            z0 += __shfl_xor_sync(0xFFFFFFFF, z0, 2);
            z1 += __shfl_xor_sync(0xFFFFFFFF, z1, 1);
            z1 += __shfl_xor_sync(0xFFFFFFFF, z1, 2);
            if (tig == 0) {
                int row = warp_m * 64 + mt * 16 + qid;
                sPart[warp_n * 128 + row]     = z0;
                sPart[warp_n * 128 + row + 8] = z1;
            }
        }
        __syncthreads();                // sPart ready; sB0/sB1 L3 reads done

        // out-store first (frees the iteration's last dependency), then tail prefetch
        if (tid < 128) {
            long long e = tile0 + tid;
            if (e < E) {
                float z = sPart[tid] + sPart[128 + tid] + sPart[256 + tid]
                        + sPart[384 + tid] + b4v;
                out[e] = 1.f / (1.f + __expf(-z));
            }
        }

        if (hasNext) {
            load_w_ca(g_wbf + W1_OFF, sB0_u);             // W1a'
            CP_COMMIT();
            load_w_cg(g_wbf + W1_OFF + 128 * 128, sB1_u); // W1b' (long lead to L1B')
            CP_COMMIT();
        }

        if (!hasNext) break;
        t = tn;
    }
}

extern "C" void kernel_launch(void* const* d_in, const int* in_sizes, int n_in,
                              void* d_out, int out_size)
{
    const float* x  = (const float*)d_in[0];
    const int*   ei = (const int*)d_in[1];
    const float* W1 = (const float*)d_in[2];
    const float* b1 = (const float*)d_in[3];
    const float* W2 = (const float*)d_in[4];
    const float* b2 = (const float*)d_in[5];
    const float* W3 = (const float*)d_in[6];
    const float* b3 = (const float*)d_in[7];
    const float* W4 = (const float*)d_in[8];
    const float* b4 = (const float*)d_in[9];
    float* out = (float*)d_out;

    int E = in_sizes[1] / 2;
    int N = in_sizes[0] / 128;
    if (N > MAX_N) N = MAX_N;

    int nTiles = (E + TILE_M - 1) / TILE_M;
    int sms = 148;
    cudaDeviceGetAttribute(&sms, cudaDevAttrMultiProcessorCount, 0);
    int grid = 2 * sms;
    if (grid > nTiles) grid = nTiles;

    int n16 = N * 8;                       // 16-float chunks in x
    int tot16 = n16 + W_TOTAL / 16;        // + weight chunks
    int prepGrid = (tot16 + 255) / 256;
    if (prepGrid > 4 * sms) prepGrid = 4 * sms;   // grid-stride
    cvt_all_kernel<<<prepGrid, 256>>>(x, W1, W2, W3, n16, tot16, (unsigned)grid);

    cudaFuncSetAttribute(edgepred_steal_kernel,
                         cudaFuncAttributeMaxDynamicSharedMemorySize, SMEM_BYTES);
    edgepred_steal_kernel<<<grid, THREADS, SMEM_BYTES>>>(
        ei, b1, b2, b3, W4, b4, out, E, N, nTiles);
}